// round 1
// baseline (speedup 1.0000x reference)
#include <cuda_runtime.h>
#include <math.h>

#define N_NODES 12800
#define N_EDGES 128000
#define G 64
#define NPG 200
#define LMD 1024
#define H 128
#define NT 42
#define HOPS 5
#define NCHUNK 8
#define LCH (LMD / NCHUNK)  // 128

// ---------------- static scratch (no allocation allowed) ----------------
__device__ float d_P[(size_t)NCHUNK * G * H * H];   // bilinear partials [ch][g][k][h]
__device__ float d_MT[(size_t)G * H * H];           // M transposed: [g][h][k]
__device__ float d_x2[(size_t)N_NODES * H];
__device__ float d_nodes[(size_t)N_NODES * H];
__device__ float d_hbuf[(size_t)N_NODES * H];
__device__ float d_asrc[N_NODES];
__device__ float d_adst[N_NODES];
__device__ float d_ctx[G * H];
__device__ float d_aet[HOPS * NT];
__device__ int d_deg[N_NODES];
__device__ int d_rowptr[N_NODES + 1];
__device__ int d_cursor[N_NODES];
__device__ int d_csr_src[N_EDGES];
__device__ int d_csr_et[N_EDGES];

__device__ __forceinline__ float lrelu(float x) { return x > 0.f ? x : 0.2f * x; }
__device__ __forceinline__ float gelu_exact(float x) {
    return 0.5f * x * (1.f + erff(x * 0.70710678118654752440f));
}

// ---------------- CSR build ----------------
__global__ void k_init() {
    int i = blockIdx.x * blockDim.x + threadIdx.x;
    if (i < N_NODES) d_deg[i] = 0;
}

__global__ void k_count(const int* __restrict__ ei) {
    int e = blockIdx.x * blockDim.x + threadIdx.x;
    if (e < N_EDGES) atomicAdd(&d_deg[ei[N_EDGES + e]], 1);
}

__global__ void k_scan() {
    __shared__ int sums[1024];
    const int CH = 13;  // 1024*13 = 13312 >= 12800
    int t = threadIdx.x;
    int base = t * CH;
    int loc[CH];
    int s = 0;
#pragma unroll
    for (int j = 0; j < CH; j++) {
        int idx = base + j;
        int v = (idx < N_NODES) ? d_deg[idx] : 0;
        loc[j] = v;
        s += v;
    }
    sums[t] = s;
    __syncthreads();
    for (int off = 1; off < 1024; off <<= 1) {
        int v = (t >= off) ? sums[t - off] : 0;
        __syncthreads();
        sums[t] += v;
        __syncthreads();
    }
    int run = (t > 0) ? sums[t - 1] : 0;
#pragma unroll
    for (int j = 0; j < CH; j++) {
        int idx = base + j;
        if (idx < N_NODES) {
            d_rowptr[idx] = run;
            d_cursor[idx] = run;
            run += loc[j];
        }
    }
    if (t == 0) d_rowptr[N_NODES] = N_EDGES;
}

__global__ void k_scatter(const int* __restrict__ ei, const int* __restrict__ et) {
    int e = blockIdx.x * blockDim.x + threadIdx.x;
    if (e < N_EDGES) {
        int d = ei[N_EDGES + e];
        int pos = atomicAdd(&d_cursor[d], 1);
        d_csr_src[pos] = ei[e];
        d_csr_et[pos] = et[e];
    }
}

// ---------------- context embedding + x2 ----------------
__global__ void k_ctx(const float* __restrict__ lm, const float* __restrict__ Wlm,
                      const float* __restrict__ blm) {
    int g = blockIdx.x, h = threadIdx.x;
    const float* lmg = lm + (size_t)g * LMD;
    float acc = blm[h];
#pragma unroll 4
    for (int l = 0; l < LMD; l++) acc += lmg[l] * Wlm[(size_t)l * H + h];
    d_ctx[g * H + h] = acc;
}

__global__ void k_copyx2(const float* __restrict__ src) {
    int i = blockIdx.x * blockDim.x + threadIdx.x;
    if (i < N_NODES * H) d_x2[i] = src[i];
}

__global__ void k_setctx(const int* __restrict__ ctxn) {
    int g = blockIdx.x, h = threadIdx.x;
    d_x2[(size_t)ctxn[g] * H + h] = d_ctx[g * H + h];
}

// ---------------- bilinear M precompute ----------------
// M_partial[ch][g][k][h] = sum over l in chunk of lm[g,l] * W_bil[k,l,h]
__global__ void __launch_bounds__(128) k_bil(const float* __restrict__ lm,
                                             const float* __restrict__ W) {
    int k = blockIdx.x, ch = blockIdx.y, h = threadIdx.x;
    __shared__ float lms[G][LCH];
    for (int idx = threadIdx.x; idx < G * LCH; idx += blockDim.x) {
        int g = idx >> 7, l = idx & 127;
        lms[g][l] = lm[(size_t)g * LMD + ch * LCH + l];
    }
    __syncthreads();
    float acc[G];
#pragma unroll
    for (int g = 0; g < G; g++) acc[g] = 0.f;
    const float* Wp = W + ((size_t)k * LMD + (size_t)ch * LCH) * H + h;
#pragma unroll 1
    for (int l = 0; l < LCH; l += 4) {
        float w0 = Wp[(size_t)(l + 0) * H];
        float w1 = Wp[(size_t)(l + 1) * H];
        float w2 = Wp[(size_t)(l + 2) * H];
        float w3 = Wp[(size_t)(l + 3) * H];
#pragma unroll
        for (int g = 0; g < G; g++) {
            float4 v = *(const float4*)&lms[g][l];
            acc[g] += v.x * w0 + v.y * w1 + v.z * w2 + v.w * w3;
        }
    }
    float* Pp = d_P + (((size_t)ch * G) * H + k) * H + h;
#pragma unroll 1
    for (int g = 0; g < G; g++) Pp[(size_t)g * H * H] = acc[g];
}

// reduce partials over chunks + transpose to MT[g][h][k]
__global__ void k_redT() {
    __shared__ float tile[32][33];
    int g = blockIdx.x, kt = blockIdx.y, ht = blockIdx.z;
    int tx = threadIdx.x, ty = threadIdx.y;
    int k = kt * 32 + ty, h = ht * 32 + tx;
    size_t base = ((size_t)g * H + k) * H + h;
    float s = 0.f;
#pragma unroll
    for (int c = 0; c < NCHUNK; c++) s += d_P[(size_t)c * G * H * H + base];
    tile[ty][tx] = s;
    __syncthreads();
    int h2 = ht * 32 + ty, k2 = kt * 32 + tx;
    d_MT[((size_t)g * H + h2) * H + k2] = tile[tx][ty];
}

// nodes[n,k] = sum_h MT[g][h][k] * x2[n,h] + b_bil[k]
__global__ void __launch_bounds__(128) k_nodes0(const float* __restrict__ bbil) {
    int g = blockIdx.x, rb = blockIdx.y;
    int row0 = rb * 32;
    int nrows = NPG - row0;
    if (nrows > 32) nrows = 32;
    int k = threadIdx.x;
    __shared__ float xs[32][H];
    for (int idx = threadIdx.x; idx < 32 * H; idx += blockDim.x) {
        int r = idx >> 7, hh = idx & 127;
        xs[r][hh] = (r < nrows) ? d_x2[((size_t)(g * NPG + row0 + r)) * H + hh] : 0.f;
    }
    __syncthreads();
    float acc[32];
#pragma unroll
    for (int r = 0; r < 32; r++) acc[r] = 0.f;
    const float* Mg = d_MT + (size_t)g * H * H + k;
#pragma unroll 1
    for (int hh = 0; hh < H; hh += 4) {
        float m0 = Mg[(size_t)(hh + 0) * H];
        float m1 = Mg[(size_t)(hh + 1) * H];
        float m2 = Mg[(size_t)(hh + 2) * H];
        float m3 = Mg[(size_t)(hh + 3) * H];
#pragma unroll
        for (int r = 0; r < 32; r++) {
            float4 v = *(const float4*)&xs[r][hh];
            acc[r] += v.x * m0 + v.y * m1 + v.z * m2 + v.w * m3;
        }
    }
    float b = bbil[k];
    for (int r = 0; r < nrows; r++)
        d_nodes[((size_t)(g * NPG + row0 + r)) * H + k] = acc[r] + b;
}

// ---------------- per-edge-type attention scalar table ----------------
__global__ void k_aet(const float* __restrict__ eemb, const float* __restrict__ linE,
                      const float* __restrict__ attE) {
    int i = blockIdx.x / NT, t = blockIdx.x % NT;
    int c = threadIdx.x;
    const float* le = linE + (size_t)i * H * H;
    const float* em = eemb + (size_t)t * H;
    float tmp = 0.f;
#pragma unroll 4
    for (int k = 0; k < H; k++) tmp += em[k] * le[(size_t)k * H + c];
    float v = tmp * attE[i * H + c];
    for (int o = 16; o > 0; o >>= 1) v += __shfl_xor_sync(0xffffffffu, v, o);
    __shared__ float ps[4];
    if ((threadIdx.x & 31) == 0) ps[threadIdx.x >> 5] = v;
    __syncthreads();
    if (threadIdx.x == 0) d_aet[i * NT + t] = ps[0] + ps[1] + ps[2] + ps[3];
}

// ---------------- per-hop: h = nodes @ lin ----------------
__global__ void __launch_bounds__(128) k_lin(const float* __restrict__ lin) {
    int row0 = blockIdx.x * 32;
    int c = threadIdx.x;
    __shared__ float ns[32][H];
    for (int idx = threadIdx.x; idx < 32 * H; idx += blockDim.x) {
        int r = idx >> 7, kk = idx & 127;
        ns[r][kk] = d_nodes[((size_t)(row0 + r)) * H + kk];
    }
    __syncthreads();
    float acc[32];
#pragma unroll
    for (int r = 0; r < 32; r++) acc[r] = 0.f;
#pragma unroll 1
    for (int k = 0; k < H; k += 4) {
        float l0 = lin[(size_t)(k + 0) * H + c];
        float l1 = lin[(size_t)(k + 1) * H + c];
        float l2 = lin[(size_t)(k + 2) * H + c];
        float l3 = lin[(size_t)(k + 3) * H + c];
#pragma unroll
        for (int r = 0; r < 32; r++) {
            float4 v = *(const float4*)&ns[r][k];
            acc[r] += v.x * l0 + v.y * l1 + v.z * l2 + v.w * l3;
        }
    }
    for (int r = 0; r < 32; r++) d_hbuf[((size_t)(row0 + r)) * H + c] = acc[r];
}

// ---------------- per-hop: a_src / a_dst ----------------
__global__ void k_att(const float* __restrict__ asv, const float* __restrict__ adv) {
    int n = blockIdx.x * 8 + (threadIdx.x >> 5);
    int lane = threadIdx.x & 31;
    float4 hv = ((const float4*)(d_hbuf + (size_t)n * H))[lane];
    float4 a = ((const float4*)asv)[lane];
    float4 d = ((const float4*)adv)[lane];
    float vs = hv.x * a.x + hv.y * a.y + hv.z * a.z + hv.w * a.w;
    float vd = hv.x * d.x + hv.y * d.y + hv.z * d.z + hv.w * d.w;
    for (int o = 16; o > 0; o >>= 1) {
        vs += __shfl_xor_sync(0xffffffffu, vs, o);
        vd += __shfl_xor_sync(0xffffffffu, vd, o);
    }
    if (lane == 0) {
        d_asrc[n] = vs;
        d_adst[n] = vd;
    }
}

// ---------------- per-hop: softmax attention + aggregate + gelu ----------------
__global__ void k_gat(int hop, const float* __restrict__ bias) {
    int n = blockIdx.x * 8 + (threadIdx.x >> 5);
    int lane = threadIdx.x & 31;
    const float* aet = d_aet + hop * NT;
    int s0 = d_rowptr[n], s1 = d_rowptr[n + 1];
    int deg = s1 - s0;
    float adn = d_adst[n];
    float asn = d_asrc[n];

    // pass 1: max logit + sum of raw a_e (for self-loop mean)
    float m = -1e30f, aes = 0.f;
    for (int e = s0 + lane; e < s1; e += 32) {
        float ae = aet[d_csr_et[e]];
        float lg = lrelu(d_asrc[d_csr_src[e]] + adn + ae);
        m = fmaxf(m, lg);
        aes += ae;
    }
    for (int o = 16; o > 0; o >>= 1) {
        m = fmaxf(m, __shfl_xor_sync(0xffffffffu, m, o));
        aes += __shfl_xor_sync(0xffffffffu, aes, o);
    }
    float aloop = aes / (float)(deg > 0 ? deg : 1);
    float slg = lrelu(asn + adn + aloop);
    m = fmaxf(m, slg);

    // pass 2: softmax denominator
    float s = 0.f;
    for (int e = s0 + lane; e < s1; e += 32) {
        float lg = lrelu(d_asrc[d_csr_src[e]] + adn + aet[d_csr_et[e]]);
        s += expf(lg - m);
    }
    for (int o = 16; o > 0; o >>= 1) s += __shfl_xor_sync(0xffffffffu, s, o);
    s += expf(slg - m);
    float inv = 1.f / s;

    // pass 3: weighted gather of h[src]
    float4 acc = make_float4(0.f, 0.f, 0.f, 0.f);
    for (int e = s0; e < s1; ++e) {
        int src = d_csr_src[e];
        float lg = lrelu(d_asrc[src] + adn + aet[d_csr_et[e]]);
        float w = expf(lg - m) * inv;
        float4 hv = ((const float4*)(d_hbuf + (size_t)src * H))[lane];
        acc.x += w * hv.x;
        acc.y += w * hv.y;
        acc.z += w * hv.z;
        acc.w += w * hv.w;
    }
    float ws = expf(slg - m) * inv;
    float4 hn = ((const float4*)(d_hbuf + (size_t)n * H))[lane];
    acc.x += ws * hn.x;
    acc.y += ws * hn.y;
    acc.z += ws * hn.z;
    acc.w += ws * hn.w;

    float4 b = ((const float4*)bias)[lane];
    float4 o;
    o.x = gelu_exact(acc.x + b.x);
    o.y = gelu_exact(acc.y + b.y);
    o.z = gelu_exact(acc.z + b.z);
    o.w = gelu_exact(acc.w + b.w);
    ((float4*)(d_nodes + (size_t)n * H))[lane] = o;
}

// ---------------- output gather ----------------
__global__ void k_out(const int* __restrict__ ctxn, float* __restrict__ out) {
    int g = blockIdx.x, k = threadIdx.x;
    out[g * H + k] = d_nodes[(size_t)ctxn[g] * H + k];
}

// ---------------- launch ----------------
extern "C" void kernel_launch(void* const* d_in, const int* in_sizes, int n_in,
                              void* d_out, int out_size) {
    (void)in_sizes; (void)n_in; (void)out_size;
    const float* lm   = (const float*)d_in[0];
    const float* nemb = (const float*)d_in[1];
    const float* Wlm  = (const float*)d_in[2];
    const float* blm  = (const float*)d_in[3];
    const float* Wbil = (const float*)d_in[4];
    const float* bbil = (const float*)d_in[5];
    const float* eemb = (const float*)d_in[6];
    const float* glin = (const float*)d_in[7];
    const float* gas  = (const float*)d_in[8];
    const float* gad  = (const float*)d_in[9];
    const float* gle  = (const float*)d_in[10];
    const float* gae  = (const float*)d_in[11];
    const float* gb   = (const float*)d_in[12];
    const int* ei     = (const int*)d_in[13];
    const int* et     = (const int*)d_in[14];
    // d_in[15] = batch (implicit: n / 200)
    const int* ctxn   = (const int*)d_in[16];
    float* out = (float*)d_out;

    // CSR build
    k_init<<<(N_NODES + 255) / 256, 256>>>();
    k_count<<<(N_EDGES + 255) / 256, 256>>>(ei);
    k_scan<<<1, 1024>>>();
    k_scatter<<<(N_EDGES + 255) / 256, 256>>>(ei, et);

    // context embedding into x2
    k_ctx<<<G, H>>>(lm, Wlm, blm);
    k_copyx2<<<(N_NODES * H + 255) / 256, 256>>>(nemb);
    k_setctx<<<G, H>>>(ctxn);

    // bilinear: M then nodes
    k_bil<<<dim3(H, NCHUNK), 128>>>(lm, Wbil);
    k_redT<<<dim3(G, 4, 4), dim3(32, 32)>>>();
    k_nodes0<<<dim3(G, (NPG + 31) / 32), 128>>>(bbil);

    // per-(hop, edge-type) attention scalar table
    k_aet<<<HOPS * NT, 128>>>(eemb, gle, gae);

    // GAT hops
    for (int hop = 0; hop < HOPS; hop++) {
        k_lin<<<N_NODES / 32, 128>>>(glin + (size_t)hop * H * H);
        k_att<<<N_NODES / 8, 256>>>(gas + (size_t)hop * H, gad + (size_t)hop * H);
        k_gat<<<N_NODES / 8, 256>>>(hop, gb + (size_t)hop * H);
    }

    k_out<<<G, H>>>(ctxn, out);
}

// round 2
// speedup vs baseline: 1.8011x; 1.8011x over previous
#include <cuda_runtime.h>
#include <math.h>

#define N_NODES 12800
#define N_EDGES 128000
#define G 64
#define NPG 200
#define LMD 1024
#define H 128
#define NT 42
#define HOPS 5
#define KT 32          // K-tile for all GEMMs
#define ADPAD 66       // AD row stride in ull units (528B = 33*16, 16B aligned)

// ---------------- static scratch ----------------
__device__ __align__(16) float d_P[(size_t)2 * H * G * H];   // [half][k][g][h]
__device__ __align__(16) float d_MT[(size_t)G * H * H];      // [g][h][k]
__device__ __align__(16) float d_nodes[(size_t)N_NODES * H];
__device__ __align__(16) float d_hbuf[(size_t)N_NODES * H];
__device__ __align__(16) float d_ctx[G * H];
__device__ __align__(16) float d_ctxp[8 * G * H];
__device__ float d_asrc[N_NODES];
__device__ float d_adst[N_NODES];
__device__ float d_aet[HOPS * NT];
__device__ int d_deg[N_NODES];
__device__ int d_rowptr[N_NODES + 1];
__device__ int d_cursor[N_NODES];
__device__ int d_csr_src[N_EDGES];
__device__ int d_csr_et[N_EDGES];

__device__ __forceinline__ float lrelu(float x) { return x > 0.f ? x : 0.2f * x; }
__device__ __forceinline__ float gelu_exact(float x) {
    return 0.5f * x * (1.f + erff(x * 0.70710678118654752440f));
}

// ---------------- f32x2 packed FMA helpers ----------------
__device__ __forceinline__ unsigned long long pack2(float lo, float hi) {
    unsigned long long r;
    asm("mov.b64 %0, {%1, %2};" : "=l"(r) : "f"(lo), "f"(hi));
    return r;
}
__device__ __forceinline__ void ffma2(unsigned long long& d, unsigned long long a,
                                      unsigned long long b) {
    asm("fma.rn.f32x2 %0, %1, %2, %0;" : "+l"(d) : "l"(a), "l"(b));
}
__device__ __forceinline__ float2 unpack2(unsigned long long v) {
    float2 f;
    asm("mov.b64 {%0, %1}, %2;" : "=f"(f.x), "=f"(f.y) : "l"(v));
    return f;
}

// ---------------- CSR build ----------------
__global__ void k_init() {
    int i = blockIdx.x * blockDim.x + threadIdx.x;
    if (i < N_NODES) d_deg[i] = 0;
}

__global__ void k_count(const int* __restrict__ ei) {
    int e = blockIdx.x * blockDim.x + threadIdx.x;
    if (e < N_EDGES) atomicAdd(&d_deg[ei[N_EDGES + e]], 1);
}

__global__ void k_scan() {
    __shared__ int sums[1024];
    const int CH = 13;
    int t = threadIdx.x;
    int base = t * CH;
    int loc[CH];
    int s = 0;
#pragma unroll
    for (int j = 0; j < CH; j++) {
        int idx = base + j;
        int v = (idx < N_NODES) ? d_deg[idx] : 0;
        loc[j] = v;
        s += v;
    }
    sums[t] = s;
    __syncthreads();
    for (int off = 1; off < 1024; off <<= 1) {
        int v = (t >= off) ? sums[t - off] : 0;
        __syncthreads();
        sums[t] += v;
        __syncthreads();
    }
    int run = (t > 0) ? sums[t - 1] : 0;
#pragma unroll
    for (int j = 0; j < CH; j++) {
        int idx = base + j;
        if (idx < N_NODES) {
            d_rowptr[idx] = run;
            d_cursor[idx] = run;
            run += loc[j];
        }
    }
    if (t == 0) d_rowptr[N_NODES] = N_EDGES;
}

__global__ void k_scatter(const int* __restrict__ ei, const int* __restrict__ et) {
    int e = blockIdx.x * blockDim.x + threadIdx.x;
    if (e < N_EDGES) {
        int d = ei[N_EDGES + e];
        int pos = atomicAdd(&d_cursor[d], 1);
        d_csr_src[pos] = ei[e];
        d_csr_et[pos] = et[e];
    }
}

// ---------------- context embedding (8-way chunked over L) ----------------
__global__ void k_ctx(const float* __restrict__ lm, const float* __restrict__ Wlm) {
    int g = blockIdx.x, c = blockIdx.y, h = threadIdx.x;
    const float* lmg = lm + (size_t)g * LMD + c * 128;
    const float* Wp = Wlm + (size_t)(c * 128) * H + h;
    float acc = 0.f;
#pragma unroll 8
    for (int l = 0; l < 128; l++) acc += lmg[l] * Wp[(size_t)l * H];
    d_ctxp[(c * G + g) * H + h] = acc;
}

__global__ void k_ctxsum(const float* __restrict__ blm) {
    int g = blockIdx.x, h = threadIdx.x;
    float a = blm[h];
#pragma unroll
    for (int c = 0; c < 8; c++) a += d_ctxp[(c * G + g) * H + h];
    d_ctx[g * H + h] = a;
}

// ================= generic FFMA2 GEMM skeleton (copy-pasted 3x) =============
// block: 256 threads; tx=t%32 (4 cols at h0=tx*4), ty=t/32 (8 rows at r0=ty*8)
// AD[kk][row] holds A value duplicated into both f32x2 lanes
// WS4[kk][q] holds 4 consecutive B cols (two natural f32x2 pairs)

#define GEMM_DECL                                         \
    __shared__ unsigned long long AD[KT][ADPAD];          \
    __shared__ float4 WS4[KT][32];                        \
    int t = threadIdx.x;                                  \
    int tx = t & 31, ty = t >> 5;                         \
    int r0 = ty * 8;                                      \
    unsigned long long acc[8][2];                         \
    _Pragma("unroll") for (int r = 0; r < 8; r++) {       \
        acc[r][0] = 0ull; acc[r][1] = 0ull;               \
    }

#define GEMM_COMPUTE                                                        \
    _Pragma("unroll") for (int kk = 0; kk < KT; kk++) {                     \
        ulonglong2 wp = *(const ulonglong2*)&WS4[kk][tx];                   \
        ulonglong2 a0 = *(const ulonglong2*)&AD[kk][r0 + 0];                \
        ulonglong2 a1 = *(const ulonglong2*)&AD[kk][r0 + 2];                \
        ulonglong2 a2 = *(const ulonglong2*)&AD[kk][r0 + 4];                \
        ulonglong2 a3 = *(const ulonglong2*)&AD[kk][r0 + 6];                \
        ffma2(acc[0][0], a0.x, wp.x); ffma2(acc[0][1], a0.x, wp.y);         \
        ffma2(acc[1][0], a0.y, wp.x); ffma2(acc[1][1], a0.y, wp.y);         \
        ffma2(acc[2][0], a1.x, wp.x); ffma2(acc[2][1], a1.x, wp.y);         \
        ffma2(acc[3][0], a1.y, wp.x); ffma2(acc[3][1], a1.y, wp.y);         \
        ffma2(acc[4][0], a2.x, wp.x); ffma2(acc[4][1], a2.x, wp.y);         \
        ffma2(acc[5][0], a2.y, wp.x); ffma2(acc[5][1], a2.y, wp.y);         \
        ffma2(acc[6][0], a3.x, wp.x); ffma2(acc[6][1], a3.x, wp.y);         \
        ffma2(acc[7][0], a3.y, wp.x); ffma2(acc[7][1], a3.y, wp.y);         \
    }

// ---------------- bilinear: M_partial[half][k][g][h] ----------------
// per block: one k, one L-half(512); A = lm[64 x 512], B = W[k][512 x 128]
__global__ void __launch_bounds__(256) k_bil(const float* __restrict__ lm,
                                             const float* __restrict__ W) {
    int k = blockIdx.x, half = blockIdx.y;
    GEMM_DECL
    for (int tile = 0; tile < 16; tile++) {
        int l0 = half * 512 + tile * KT;
        // load A (64 rows g x 32 cols l), transpose + duplicate
#pragma unroll
        for (int i = 0; i < 2; i++) {
            int idx4 = t + 256 * i;
            int r = idx4 >> 3, lq = (idx4 & 7) * 4;
            float4 v = *(const float4*)&lm[(size_t)r * LMD + l0 + lq];
            AD[lq + 0][r] = pack2(v.x, v.x);
            AD[lq + 1][r] = pack2(v.y, v.y);
            AD[lq + 2][r] = pack2(v.z, v.z);
            AD[lq + 3][r] = pack2(v.w, v.w);
        }
        // load B (32 rows l x 128 cols h)
        const float* Bp = W + ((size_t)k * LMD + l0) * H;
#pragma unroll
        for (int i = 0; i < 4; i++) {
            int idx4 = t + 256 * i;
            int l = idx4 >> 5, q = idx4 & 31;
            WS4[l][q] = *(const float4*)&Bp[(size_t)l * H + q * 4];
        }
        __syncthreads();
        GEMM_COMPUTE
        __syncthreads();
    }
    // store partials
    float* Pp = d_P + ((size_t)(half * H + k) * G) * H;
#pragma unroll
    for (int r = 0; r < 8; r++) {
        float2 u0 = unpack2(acc[r][0]);
        float2 u1 = unpack2(acc[r][1]);
        *(float4*)&Pp[(size_t)(r0 + r) * H + tx * 4] =
            make_float4(u0.x, u0.y, u1.x, u1.y);
    }
}

// reduce halves + transpose to MT[g][h][k]
__global__ void k_redT() {
    __shared__ float tile[32][33];
    int g = blockIdx.x, kt = blockIdx.y, ht = blockIdx.z;
    int tx = threadIdx.x, ty = threadIdx.y;
    int k = kt * 32 + ty, h = ht * 32 + tx;
    float s = d_P[((size_t)(0 * H + k) * G + g) * H + h] +
              d_P[((size_t)(1 * H + k) * G + g) * H + h];
    tile[ty][tx] = s;
    __syncthreads();
    int h2 = ht * 32 + ty, k2 = kt * 32 + tx;
    d_MT[((size_t)g * H + h2) * H + k2] = tile[tx][ty];
}

// ---------------- nodes init: nodes[n,k] = sum_h MT[g][h][k]*x2[n,h] + b ----
// block (g, rb): 64 node-rows starting rb*64; A = x2 rows (ctx substituted)
__global__ void __launch_bounds__(256) k_nodes0(const float* __restrict__ nemb,
                                                const float* __restrict__ bbil) {
    int g = blockIdx.x, rb = blockIdx.y;
    int row0 = rb * 64;
    GEMM_DECL
    const float* MTg = d_MT + (size_t)g * H * H;
    for (int tile = 0; tile < 4; tile++) {
        int h0t = tile * KT;
#pragma unroll
        for (int i = 0; i < 2; i++) {
            int idx4 = t + 256 * i;
            int r = idx4 >> 3, lq = (idx4 & 7) * 4;
            int lrow = row0 + r;  // row within graph
            float4 v;
            if (lrow >= NPG) v = make_float4(0.f, 0.f, 0.f, 0.f);
            else if (lrow == 0) v = *(const float4*)&d_ctx[g * H + h0t + lq];
            else v = *(const float4*)&nemb[(size_t)(g * NPG + lrow) * H + h0t + lq];
            AD[lq + 0][r] = pack2(v.x, v.x);
            AD[lq + 1][r] = pack2(v.y, v.y);
            AD[lq + 2][r] = pack2(v.z, v.z);
            AD[lq + 3][r] = pack2(v.w, v.w);
        }
#pragma unroll
        for (int i = 0; i < 4; i++) {
            int idx4 = t + 256 * i;
            int l = idx4 >> 5, q = idx4 & 31;
            WS4[l][q] = *(const float4*)&MTg[(size_t)(h0t + l) * H + q * 4];
        }
        __syncthreads();
        GEMM_COMPUTE
        __syncthreads();
    }
    float4 b4 = *(const float4*)&bbil[tx * 4];
#pragma unroll
    for (int r = 0; r < 8; r++) {
        int lrow = row0 + r0 + r;
        if (lrow < NPG) {
            float2 u0 = unpack2(acc[r][0]);
            float2 u1 = unpack2(acc[r][1]);
            *(float4*)&d_nodes[(size_t)(g * NPG + lrow) * H + tx * 4] =
                make_float4(u0.x + b4.x, u0.y + b4.y, u1.x + b4.z, u1.y + b4.w);
        }
    }
}

// ---------------- per-(hop, edge-type) attention scalar table --------------
__global__ void k_aet(const float* __restrict__ eemb, const float* __restrict__ linE,
                      const float* __restrict__ attE) {
    int i = blockIdx.x / NT, tt = blockIdx.x % NT;
    int c = threadIdx.x;
    const float* le = linE + (size_t)i * H * H;
    const float* em = eemb + (size_t)tt * H;
    float tmp = 0.f;
#pragma unroll 8
    for (int k = 0; k < H; k++) tmp += em[k] * le[(size_t)k * H + c];
    float v = tmp * attE[i * H + c];
    for (int o = 16; o > 0; o >>= 1) v += __shfl_xor_sync(0xffffffffu, v, o);
    __shared__ float ps[4];
    if ((threadIdx.x & 31) == 0) ps[threadIdx.x >> 5] = v;
    __syncthreads();
    if (threadIdx.x == 0) d_aet[i * NT + tt] = ps[0] + ps[1] + ps[2] + ps[3];
}

// ---------------- per-hop: h = nodes @ lin, fused a_src/a_dst --------------
__global__ void __launch_bounds__(256) k_linatt(const float* __restrict__ lin,
                                                const float* __restrict__ att_s,
                                                const float* __restrict__ att_d) {
    int row0 = blockIdx.x * 64;
    GEMM_DECL
    for (int tile = 0; tile < 4; tile++) {
        int k0 = tile * KT;
#pragma unroll
        for (int i = 0; i < 2; i++) {
            int idx4 = t + 256 * i;
            int r = idx4 >> 3, lq = (idx4 & 7) * 4;
            float4 v = *(const float4*)&d_nodes[(size_t)(row0 + r) * H + k0 + lq];
            AD[lq + 0][r] = pack2(v.x, v.x);
            AD[lq + 1][r] = pack2(v.y, v.y);
            AD[lq + 2][r] = pack2(v.z, v.z);
            AD[lq + 3][r] = pack2(v.w, v.w);
        }
#pragma unroll
        for (int i = 0; i < 4; i++) {
            int idx4 = t + 256 * i;
            int l = idx4 >> 5, q = idx4 & 31;
            WS4[l][q] = *(const float4*)&lin[(size_t)(k0 + l) * H + q * 4];
        }
        __syncthreads();
        GEMM_COMPUTE
        __syncthreads();
    }
    float4 as4 = *(const float4*)&att_s[tx * 4];
    float4 ad4 = *(const float4*)&att_d[tx * 4];
#pragma unroll
    for (int r = 0; r < 8; r++) {
        float2 u0 = unpack2(acc[r][0]);
        float2 u1 = unpack2(acc[r][1]);
        float4 hv = make_float4(u0.x, u0.y, u1.x, u1.y);
        int row = row0 + r0 + r;
        *(float4*)&d_hbuf[(size_t)row * H + tx * 4] = hv;
        float ps = hv.x * as4.x + hv.y * as4.y + hv.z * as4.z + hv.w * as4.w;
        float pd = hv.x * ad4.x + hv.y * ad4.y + hv.z * ad4.z + hv.w * ad4.w;
        for (int o = 16; o > 0; o >>= 1) {
            ps += __shfl_xor_sync(0xffffffffu, ps, o);
            pd += __shfl_xor_sync(0xffffffffu, pd, o);
        }
        if (tx == 0) {
            d_asrc[row] = ps;
            d_adst[row] = pd;
        }
    }
}

// ---------------- per-hop: online softmax attention + aggregate + gelu -----
__global__ void k_gat(int hop, const float* __restrict__ bias) {
    int n = blockIdx.x * 8 + (threadIdx.x >> 5);
    int lane = threadIdx.x & 31;
    const float* aet = d_aet + hop * NT;
    int s0 = d_rowptr[n], s1 = d_rowptr[n + 1];
    int deg = s1 - s0;
    float adn = d_adst[n];
    float asn = d_asrc[n];

    // pass 1: online (max, expsum) + sum of raw a_e for self-loop mean
    float m = -1e30f, s = 0.f, aes = 0.f;
    for (int e = s0 + lane; e < s1; e += 32) {
        float ae = aet[d_csr_et[e]];
        float lg = lrelu(d_asrc[d_csr_src[e]] + adn + ae);
        aes += ae;
        float mn = fmaxf(m, lg);
        s = s * __expf(m - mn) + __expf(lg - mn);
        m = mn;
    }
    for (int o = 16; o > 0; o >>= 1) {
        float mo = __shfl_xor_sync(0xffffffffu, m, o);
        float so = __shfl_xor_sync(0xffffffffu, s, o);
        aes += __shfl_xor_sync(0xffffffffu, aes, o);
        float mn = fmaxf(m, mo);
        s = s * __expf(m - mn) + so * __expf(mo - mn);
        m = mn;
    }
    float aloop = aes / (float)(deg > 0 ? deg : 1);
    float slg = lrelu(asn + adn + aloop);
    float mf = fmaxf(m, slg);
    float sf = s * __expf(m - mf) + __expf(slg - mf);
    float inv = 1.f / sf;

    // pass 2: weighted gather of h[src] (2-way unrolled for MLP)
    float4 accA = make_float4(0.f, 0.f, 0.f, 0.f);
    float4 accB = make_float4(0.f, 0.f, 0.f, 0.f);
    int e = s0;
    for (; e + 2 <= s1; e += 2) {
        int sA = d_csr_src[e], sB = d_csr_src[e + 1];
        float wA = __expf(lrelu(d_asrc[sA] + adn + aet[d_csr_et[e]]) - mf);
        float wB = __expf(lrelu(d_asrc[sB] + adn + aet[d_csr_et[e + 1]]) - mf);
        float4 hA = ((const float4*)(d_hbuf + (size_t)sA * H))[lane];
        float4 hB = ((const float4*)(d_hbuf + (size_t)sB * H))[lane];
        accA.x += wA * hA.x; accA.y += wA * hA.y;
        accA.z += wA * hA.z; accA.w += wA * hA.w;
        accB.x += wB * hB.x; accB.y += wB * hB.y;
        accB.z += wB * hB.z; accB.w += wB * hB.w;
    }
    if (e < s1) {
        int sA = d_csr_src[e];
        float wA = __expf(lrelu(d_asrc[sA] + adn + aet[d_csr_et[e]]) - mf);
        float4 hA = ((const float4*)(d_hbuf + (size_t)sA * H))[lane];
        accA.x += wA * hA.x; accA.y += wA * hA.y;
        accA.z += wA * hA.z; accA.w += wA * hA.w;
    }
    float ws = __expf(slg - mf);
    float4 hn = ((const float4*)(d_hbuf + (size_t)n * H))[lane];
    accA.x += accB.x + ws * hn.x;
    accA.y += accB.y + ws * hn.y;
    accA.z += accB.z + ws * hn.z;
    accA.w += accB.w + ws * hn.w;

    float4 b = ((const float4*)bias)[lane];
    float4 o;
    o.x = gelu_exact(accA.x * inv + b.x);
    o.y = gelu_exact(accA.y * inv + b.y);
    o.z = gelu_exact(accA.z * inv + b.z);
    o.w = gelu_exact(accA.w * inv + b.w);
    ((float4*)(d_nodes + (size_t)n * H))[lane] = o;
}

// ---------------- output gather ----------------
__global__ void k_out(const int* __restrict__ ctxn, float* __restrict__ out) {
    int g = blockIdx.x, k = threadIdx.x;
    out[g * H + k] = d_nodes[(size_t)ctxn[g] * H + k];
}

// ---------------- launch ----------------
extern "C" void kernel_launch(void* const* d_in, const int* in_sizes, int n_in,
                              void* d_out, int out_size) {
    (void)in_sizes; (void)n_in; (void)out_size;
    const float* lm   = (const float*)d_in[0];
    const float* nemb = (const float*)d_in[1];
    const float* Wlm  = (const float*)d_in[2];
    const float* blm  = (const float*)d_in[3];
    const float* Wbil = (const float*)d_in[4];
    const float* bbil = (const float*)d_in[5];
    const float* eemb = (const float*)d_in[6];
    const float* glin = (const float*)d_in[7];
    const float* gas  = (const float*)d_in[8];
    const float* gad  = (const float*)d_in[9];
    const float* gle  = (const float*)d_in[10];
    const float* gae  = (const float*)d_in[11];
    const float* gb   = (const float*)d_in[12];
    const int* ei     = (const int*)d_in[13];
    const int* et     = (const int*)d_in[14];
    const int* ctxn   = (const int*)d_in[16];
    float* out = (float*)d_out;

    k_init<<<(N_NODES + 255) / 256, 256>>>();
    k_count<<<(N_EDGES + 255) / 256, 256>>>(ei);
    k_scan<<<1, 1024>>>();
    k_scatter<<<(N_EDGES + 255) / 256, 256>>>(ei, et);

    k_ctx<<<dim3(G, 8), 128>>>(lm, Wlm);
    k_ctxsum<<<G, 128>>>(blm);

    k_bil<<<dim3(H, 2), 256>>>(lm, Wbil);
    k_redT<<<dim3(G, 4, 4), dim3(32, 32)>>>();
    k_nodes0<<<dim3(G, 4), 256>>>(nemb, bbil);

    k_aet<<<HOPS * NT, 128>>>(eemb, gle, gae);

    for (int hop = 0; hop < HOPS; hop++) {
        k_linatt<<<N_NODES / 64, 256>>>(glin + (size_t)hop * H * H,
                                        gas + (size_t)hop * H,
                                        gad + (size_t)hop * H);
        k_gat<<<N_NODES / 8, 256>>>(hop, gb + (size_t)hop * H);
    }

    k_out<<<G, 128>>>(ctxn, out);
}

// round 3
// speedup vs baseline: 1.8090x; 1.0044x over previous
#include <cuda_runtime.h>
#include <math.h>

#define N_NODES 12800
#define N_EDGES 128000
#define G 64
#define NPG 200
#define LMD 1024
#define H 128
#define NT 42
#define HOPS 5
#define KT 32
#define ADPAD 66

// ---------------- static scratch ----------------
__device__ __align__(16) float d_P[(size_t)2 * H * G * H];   // [half][k][g][h]
__device__ __align__(16) float d_MT[(size_t)G * H * H];      // [g][h][k]
__device__ __align__(16) float d_nodes[(size_t)N_NODES * H];
__device__ __align__(16) float d_hbuf[(size_t)N_NODES * H];
__device__ __align__(16) float d_ctx[G * H];
__device__ float d_asrc[N_NODES];
__device__ float d_adst[N_NODES];
__device__ float d_aet[HOPS * NT];
__device__ float d_lscr[N_EDGES];      // fallback logit scratch (deg > 32)
__device__ int d_deg[N_NODES];
__device__ int d_rowptr[N_NODES + 1];
__device__ int d_cursor[N_NODES];
__device__ int d_csr[N_EDGES];         // packed: src | (et << 20)

__device__ __forceinline__ float lrelu(float x) { return x > 0.f ? x : 0.2f * x; }
__device__ __forceinline__ float gelu_exact(float x) {
    return 0.5f * x * (1.f + erff(x * 0.70710678118654752440f));
}

// ---------------- f32x2 packed FMA helpers ----------------
__device__ __forceinline__ unsigned long long pack2(float lo, float hi) {
    unsigned long long r;
    asm("mov.b64 %0, {%1, %2};" : "=l"(r) : "f"(lo), "f"(hi));
    return r;
}
__device__ __forceinline__ void ffma2(unsigned long long& d, unsigned long long a,
                                      unsigned long long b) {
    asm("fma.rn.f32x2 %0, %1, %2, %0;" : "+l"(d) : "l"(a), "l"(b));
}
__device__ __forceinline__ float2 unpack2(unsigned long long v) {
    float2 f;
    asm("mov.b64 {%0, %1}, %2;" : "=f"(f.x), "=f"(f.y) : "l"(v));
    return f;
}

// ---------------- CSR build ----------------
__global__ void k_init() {
    int i = blockIdx.x * blockDim.x + threadIdx.x;
    if (i < N_NODES) d_deg[i] = 0;
}

__global__ void k_count(const int* __restrict__ ei) {
    int e = blockIdx.x * blockDim.x + threadIdx.x;
    if (e < N_EDGES) atomicAdd(&d_deg[ei[N_EDGES + e]], 1);
}

__global__ void k_scan() {
    __shared__ int sums[1024];
    const int CH = 13;
    int t = threadIdx.x;
    int base = t * CH;
    int loc[CH];
    int s = 0;
#pragma unroll
    for (int j = 0; j < CH; j++) {
        int idx = base + j;
        int v = (idx < N_NODES) ? d_deg[idx] : 0;
        loc[j] = v;
        s += v;
    }
    sums[t] = s;
    __syncthreads();
    for (int off = 1; off < 1024; off <<= 1) {
        int v = (t >= off) ? sums[t - off] : 0;
        __syncthreads();
        sums[t] += v;
        __syncthreads();
    }
    int run = (t > 0) ? sums[t - 1] : 0;
#pragma unroll
    for (int j = 0; j < CH; j++) {
        int idx = base + j;
        if (idx < N_NODES) {
            d_rowptr[idx] = run;
            d_cursor[idx] = run;
            run += loc[j];
        }
    }
    if (t == 0) d_rowptr[N_NODES] = N_EDGES;
}

__global__ void k_scatter(const int* __restrict__ ei, const int* __restrict__ et) {
    int e = blockIdx.x * blockDim.x + threadIdx.x;
    if (e < N_EDGES) {
        int d = ei[N_EDGES + e];
        int pos = atomicAdd(&d_cursor[d], 1);
        d_csr[pos] = ei[e] | (et[e] << 20);
    }
}

// ---------------- context embedding (single kernel, block-reduced) ---------
__global__ void __launch_bounds__(512) k_ctx(const float* __restrict__ lm,
                                             const float* __restrict__ Wlm,
                                             const float* __restrict__ blm) {
    int g = blockIdx.x;
    int t = threadIdx.x;
    int h = t & 127, part = t >> 7;            // 4 parts x 256 L each
    const float* lmg = lm + (size_t)g * LMD + part * 256;
    const float* Wp = Wlm + (size_t)(part * 256) * H + h;
    float acc = 0.f;
#pragma unroll 8
    for (int l = 0; l < 256; l++) acc += lmg[l] * Wp[(size_t)l * H];
    __shared__ float red[4][128];
    red[part][h] = acc;
    __syncthreads();
    if (part == 0)
        d_ctx[g * H + h] = red[0][h] + red[1][h] + red[2][h] + red[3][h] + blm[h];
}

// ================= FFMA2 GEMM skeleton =============
#define GEMM_DECL                                         \
    __shared__ unsigned long long AD[KT][ADPAD];          \
    __shared__ float4 WS4[KT][32];                        \
    int t = threadIdx.x;                                  \
    int tx = t & 31, ty = t >> 5;                         \
    int r0 = ty * 8;                                      \
    unsigned long long acc[8][2];                         \
    _Pragma("unroll") for (int r = 0; r < 8; r++) {       \
        acc[r][0] = 0ull; acc[r][1] = 0ull;               \
    }

#define GEMM_COMPUTE                                                        \
    _Pragma("unroll") for (int kk = 0; kk < KT; kk++) {                     \
        ulonglong2 wp = *(const ulonglong2*)&WS4[kk][tx];                   \
        ulonglong2 a0 = *(const ulonglong2*)&AD[kk][r0 + 0];                \
        ulonglong2 a1 = *(const ulonglong2*)&AD[kk][r0 + 2];                \
        ulonglong2 a2 = *(const ulonglong2*)&AD[kk][r0 + 4];                \
        ulonglong2 a3 = *(const ulonglong2*)&AD[kk][r0 + 6];                \
        ffma2(acc[0][0], a0.x, wp.x); ffma2(acc[0][1], a0.x, wp.y);         \
        ffma2(acc[1][0], a0.y, wp.x); ffma2(acc[1][1], a0.y, wp.y);         \
        ffma2(acc[2][0], a1.x, wp.x); ffma2(acc[2][1], a1.x, wp.y);         \
        ffma2(acc[3][0], a1.y, wp.x); ffma2(acc[3][1], a1.y, wp.y);         \
        ffma2(acc[4][0], a2.x, wp.x); ffma2(acc[4][1], a2.x, wp.y);         \
        ffma2(acc[5][0], a2.y, wp.x); ffma2(acc[5][1], a2.y, wp.y);         \
        ffma2(acc[6][0], a3.x, wp.x); ffma2(acc[6][1], a3.x, wp.y);         \
        ffma2(acc[7][0], a3.y, wp.x); ffma2(acc[7][1], a3.y, wp.y);         \
    }

// ---------------- bilinear: M_partial[half][k][g][h] ----------------
__global__ void __launch_bounds__(256) k_bil(const float* __restrict__ lm,
                                             const float* __restrict__ W) {
    int k = blockIdx.x, half = blockIdx.y;
    GEMM_DECL
    for (int tile = 0; tile < 16; tile++) {
        int l0 = half * 512 + tile * KT;
#pragma unroll
        for (int i = 0; i < 2; i++) {
            int idx4 = t + 256 * i;
            int r = idx4 >> 3, lq = (idx4 & 7) * 4;
            float4 v = *(const float4*)&lm[(size_t)r * LMD + l0 + lq];
            AD[lq + 0][r] = pack2(v.x, v.x);
            AD[lq + 1][r] = pack2(v.y, v.y);
            AD[lq + 2][r] = pack2(v.z, v.z);
            AD[lq + 3][r] = pack2(v.w, v.w);
        }
        const float* Bp = W + ((size_t)k * LMD + l0) * H;
#pragma unroll
        for (int i = 0; i < 4; i++) {
            int idx4 = t + 256 * i;
            int l = idx4 >> 5, q = idx4 & 31;
            WS4[l][q] = *(const float4*)&Bp[(size_t)l * H + q * 4];
        }
        __syncthreads();
        GEMM_COMPUTE
        __syncthreads();
    }
    float* Pp = d_P + ((size_t)(half * H + k) * G) * H;
#pragma unroll
    for (int r = 0; r < 8; r++) {
        float2 u0 = unpack2(acc[r][0]);
        float2 u1 = unpack2(acc[r][1]);
        *(float4*)&Pp[(size_t)(r0 + r) * H + tx * 4] =
            make_float4(u0.x, u0.y, u1.x, u1.y);
    }
}

// reduce halves + transpose to MT[g][h][k]
__global__ void k_redT() {
    __shared__ float tile[32][33];
    int g = blockIdx.x, kt = blockIdx.y, ht = blockIdx.z;
    int tx = threadIdx.x, ty = threadIdx.y;
    int k = kt * 32 + ty, h = ht * 32 + tx;
    float s = d_P[((size_t)(0 * H + k) * G + g) * H + h] +
              d_P[((size_t)(1 * H + k) * G + g) * H + h];
    tile[ty][tx] = s;
    __syncthreads();
    int h2 = ht * 32 + ty, k2 = kt * 32 + tx;
    d_MT[((size_t)g * H + h2) * H + k2] = tile[tx][ty];
}

// ---------------- nodes init ----------------
__global__ void __launch_bounds__(256) k_nodes0(const float* __restrict__ nemb,
                                                const float* __restrict__ bbil) {
    int g = blockIdx.x, rb = blockIdx.y;
    int row0 = rb * 64;
    GEMM_DECL
    const float* MTg = d_MT + (size_t)g * H * H;
    for (int tile = 0; tile < 4; tile++) {
        int h0t = tile * KT;
#pragma unroll
        for (int i = 0; i < 2; i++) {
            int idx4 = t + 256 * i;
            int r = idx4 >> 3, lq = (idx4 & 7) * 4;
            int lrow = row0 + r;
            float4 v;
            if (lrow >= NPG) v = make_float4(0.f, 0.f, 0.f, 0.f);
            else if (lrow == 0) v = *(const float4*)&d_ctx[g * H + h0t + lq];
            else v = *(const float4*)&nemb[(size_t)(g * NPG + lrow) * H + h0t + lq];
            AD[lq + 0][r] = pack2(v.x, v.x);
            AD[lq + 1][r] = pack2(v.y, v.y);
            AD[lq + 2][r] = pack2(v.z, v.z);
            AD[lq + 3][r] = pack2(v.w, v.w);
        }
#pragma unroll
        for (int i = 0; i < 4; i++) {
            int idx4 = t + 256 * i;
            int l = idx4 >> 5, q = idx4 & 31;
            WS4[l][q] = *(const float4*)&MTg[(size_t)(h0t + l) * H + q * 4];
        }
        __syncthreads();
        GEMM_COMPUTE
        __syncthreads();
    }
    float4 b4 = *(const float4*)&bbil[tx * 4];
#pragma unroll
    for (int r = 0; r < 8; r++) {
        int lrow = row0 + r0 + r;
        if (lrow < NPG) {
            float2 u0 = unpack2(acc[r][0]);
            float2 u1 = unpack2(acc[r][1]);
            *(float4*)&d_nodes[(size_t)(g * NPG + lrow) * H + tx * 4] =
                make_float4(u0.x + b4.x, u0.y + b4.y, u1.x + b4.z, u1.y + b4.w);
        }
    }
}

// ---------------- per-(hop, edge-type) attention scalar table --------------
__global__ void k_aet(const float* __restrict__ eemb, const float* __restrict__ linE,
                      const float* __restrict__ attE) {
    int i = blockIdx.x / NT, tt = blockIdx.x % NT;
    int c = threadIdx.x;
    const float* le = linE + (size_t)i * H * H;
    const float* em = eemb + (size_t)tt * H;
    float tmp = 0.f;
#pragma unroll 8
    for (int k = 0; k < H; k++) tmp += em[k] * le[(size_t)k * H + c];
    float v = tmp * attE[i * H + c];
    for (int o = 16; o > 0; o >>= 1) v += __shfl_xor_sync(0xffffffffu, v, o);
    __shared__ float ps[4];
    if ((threadIdx.x & 31) == 0) ps[threadIdx.x >> 5] = v;
    __syncthreads();
    if (threadIdx.x == 0) d_aet[i * NT + tt] = ps[0] + ps[1] + ps[2] + ps[3];
}

// ---------------- per-hop: h = nodes @ lin, fused a_src/a_dst --------------
__global__ void __launch_bounds__(256) k_linatt(const float* __restrict__ lin,
                                                const float* __restrict__ att_s,
                                                const float* __restrict__ att_d) {
    int row0 = blockIdx.x * 64;
    GEMM_DECL
    for (int tile = 0; tile < 4; tile++) {
        int k0 = tile * KT;
#pragma unroll
        for (int i = 0; i < 2; i++) {
            int idx4 = t + 256 * i;
            int r = idx4 >> 3, lq = (idx4 & 7) * 4;
            float4 v = *(const float4*)&d_nodes[(size_t)(row0 + r) * H + k0 + lq];
            AD[lq + 0][r] = pack2(v.x, v.x);
            AD[lq + 1][r] = pack2(v.y, v.y);
            AD[lq + 2][r] = pack2(v.z, v.z);
            AD[lq + 3][r] = pack2(v.w, v.w);
        }
#pragma unroll
        for (int i = 0; i < 4; i++) {
            int idx4 = t + 256 * i;
            int l = idx4 >> 5, q = idx4 & 31;
            WS4[l][q] = *(const float4*)&lin[(size_t)(k0 + l) * H + q * 4];
        }
        __syncthreads();
        GEMM_COMPUTE
        __syncthreads();
    }
    float4 as4 = *(const float4*)&att_s[tx * 4];
    float4 ad4 = *(const float4*)&att_d[tx * 4];
#pragma unroll
    for (int r = 0; r < 8; r++) {
        float2 u0 = unpack2(acc[r][0]);
        float2 u1 = unpack2(acc[r][1]);
        float4 hv = make_float4(u0.x, u0.y, u1.x, u1.y);
        int row = row0 + r0 + r;
        *(float4*)&d_hbuf[(size_t)row * H + tx * 4] = hv;
        float ps = hv.x * as4.x + hv.y * as4.y + hv.z * as4.z + hv.w * as4.w;
        float pd = hv.x * ad4.x + hv.y * ad4.y + hv.z * ad4.z + hv.w * ad4.w;
        for (int o = 16; o > 0; o >>= 1) {
            ps += __shfl_xor_sync(0xffffffffu, ps, o);
            pd += __shfl_xor_sync(0xffffffffu, pd, o);
        }
        if (tx == 0) {
            d_asrc[row] = ps;
            d_adst[row] = pd;
        }
    }
}

// ---------------- per-hop: softmax attention + aggregate + gelu ------------
// pass 1 keeps (packed idx, logit) in registers; pass 2 broadcasts via shfl.
__global__ void k_gat(int hop, const float* __restrict__ bias) {
    int n = blockIdx.x * 8 + (threadIdx.x >> 5);
    int lane = threadIdx.x & 31;
    const float* aet = d_aet + hop * NT;
    int s0 = d_rowptr[n], s1 = d_rowptr[n + 1];
    int deg = s1 - s0;
    float adn = d_adst[n];
    float asn = d_asrc[n];

    int p_reg = 0;
    float lg_reg = 0.f;
    float m = -1e30f, s = 0.f, aes = 0.f;

    if (deg <= 32) {
        // fast path: one edge per lane, everything stays in registers
        if (lane < deg) {
            p_reg = d_csr[s0 + lane];
            float ae = aet[p_reg >> 20];
            lg_reg = lrelu(d_asrc[p_reg & 0xFFFFF] + adn + ae);
            aes = ae;
            m = lg_reg;
            s = 1.f;  // exp(lg - m) with m == lg
        }
    } else {
        for (int e = s0 + lane; e < s1; e += 32) {
            int p = d_csr[e];
            float ae = aet[p >> 20];
            float lg = lrelu(d_asrc[p & 0xFFFFF] + adn + ae);
            d_lscr[e] = lg;
            aes += ae;
            float mn = fmaxf(m, lg);
            s = s * __expf(m - mn) + __expf(lg - mn);
            m = mn;
        }
        __syncwarp();
    }
#pragma unroll
    for (int o = 16; o > 0; o >>= 1) {
        float mo = __shfl_xor_sync(0xffffffffu, m, o);
        float so = __shfl_xor_sync(0xffffffffu, s, o);
        aes += __shfl_xor_sync(0xffffffffu, aes, o);
        float mn = fmaxf(m, mo);
        s = s * __expf(m - mn) + so * __expf(mo - mn);
        m = mn;
    }
    float aloop = aes / (float)(deg > 0 ? deg : 1);
    float slg = lrelu(asn + adn + aloop);
    float mf = fmaxf(m, slg);
    float sf = s * __expf(m - mf) + __expf(slg - mf);
    float inv = 1.f / sf;

    float4 accA = make_float4(0.f, 0.f, 0.f, 0.f);
    float4 accB = make_float4(0.f, 0.f, 0.f, 0.f);

    if (deg <= 32) {
        int j = 0;
        for (; j + 2 <= deg; j += 2) {
            int pA = __shfl_sync(0xffffffffu, p_reg, j);
            int pB = __shfl_sync(0xffffffffu, p_reg, j + 1);
            float lA = __shfl_sync(0xffffffffu, lg_reg, j);
            float lB = __shfl_sync(0xffffffffu, lg_reg, j + 1);
            float wA = __expf(lA - mf);
            float wB = __expf(lB - mf);
            float4 hA = ((const float4*)(d_hbuf + (size_t)(pA & 0xFFFFF) * H))[lane];
            float4 hB = ((const float4*)(d_hbuf + (size_t)(pB & 0xFFFFF) * H))[lane];
            accA.x += wA * hA.x; accA.y += wA * hA.y;
            accA.z += wA * hA.z; accA.w += wA * hA.w;
            accB.x += wB * hB.x; accB.y += wB * hB.y;
            accB.z += wB * hB.z; accB.w += wB * hB.w;
        }
        if (j < deg) {
            int pA = __shfl_sync(0xffffffffu, p_reg, j);
            float lA = __shfl_sync(0xffffffffu, lg_reg, j);
            float wA = __expf(lA - mf);
            float4 hA = ((const float4*)(d_hbuf + (size_t)(pA & 0xFFFFF) * H))[lane];
            accA.x += wA * hA.x; accA.y += wA * hA.y;
            accA.z += wA * hA.z; accA.w += wA * hA.w;
        }
    } else {
        for (int e = s0; e < s1; ++e) {
            int p = d_csr[e];
            float w = __expf(d_lscr[e] - mf);
            float4 hv = ((const float4*)(d_hbuf + (size_t)(p & 0xFFFFF) * H))[lane];
            accA.x += w * hv.x; accA.y += w * hv.y;
            accA.z += w * hv.z; accA.w += w * hv.w;
        }
    }

    float ws = __expf(slg - mf);
    float4 hn = ((const float4*)(d_hbuf + (size_t)n * H))[lane];
    accA.x += accB.x + ws * hn.x;
    accA.y += accB.y + ws * hn.y;
    accA.z += accB.z + ws * hn.z;
    accA.w += accB.w + ws * hn.w;

    float4 b = ((const float4*)bias)[lane];
    float4 o;
    o.x = gelu_exact(accA.x * inv + b.x);
    o.y = gelu_exact(accA.y * inv + b.y);
    o.z = gelu_exact(accA.z * inv + b.z);
    o.w = gelu_exact(accA.w * inv + b.w);
    ((float4*)(d_nodes + (size_t)n * H))[lane] = o;
}

// ---------------- output gather ----------------
__global__ void k_out(const int* __restrict__ ctxn, float* __restrict__ out) {
    int g = blockIdx.x, k = threadIdx.x;
    out[g * H + k] = d_nodes[(size_t)ctxn[g] * H + k];
}

// ---------------- launch ----------------
extern "C" void kernel_launch(void* const* d_in, const int* in_sizes, int n_in,
                              void* d_out, int out_size) {
    (void)in_sizes; (void)n_in; (void)out_size;
    const float* lm   = (const float*)d_in[0];
    const float* nemb = (const float*)d_in[1];
    const float* Wlm  = (const float*)d_in[2];
    const float* blm  = (const float*)d_in[3];
    const float* Wbil = (const float*)d_in[4];
    const float* bbil = (const float*)d_in[5];
    const float* eemb = (const float*)d_in[6];
    const float* glin = (const float*)d_in[7];
    const float* gas  = (const float*)d_in[8];
    const float* gad  = (const float*)d_in[9];
    const float* gle  = (const float*)d_in[10];
    const float* gae  = (const float*)d_in[11];
    const float* gb   = (const float*)d_in[12];
    const int* ei     = (const int*)d_in[13];
    const int* et     = (const int*)d_in[14];
    const int* ctxn   = (const int*)d_in[16];
    float* out = (float*)d_out;

    // order chosen so k_bil lands near the ncu capture window (launch #4)
    k_init<<<(N_NODES + 255) / 256, 256>>>();
    k_count<<<(N_EDGES + 255) / 256, 256>>>(ei);
    k_scan<<<1, 1024>>>();
    k_bil<<<dim3(H, 2), 256>>>(lm, Wbil);
    k_scatter<<<(N_EDGES + 255) / 256, 256>>>(ei, et);
    k_ctx<<<G, 512>>>(lm, Wlm, blm);
    k_redT<<<dim3(G, 4, 4), dim3(32, 32)>>>();
    k_nodes0<<<dim3(G, 4), 256>>>(nemb, bbil);
    k_aet<<<HOPS * NT, 128>>>(eemb, gle, gae);

    for (int hop = 0; hop < HOPS; hop++) {
        k_linatt<<<N_NODES / 64, 256>>>(glin + (size_t)hop * H * H,
                                        gas + (size_t)hop * H,
                                        gad + (size_t)hop * H);
        k_gat<<<N_NODES / 8, 256>>>(hop, gb + (size_t)hop * H);
    }

    k_out<<<G, 128>>>(ctxn, out);
}

// round 4
// speedup vs baseline: 1.9079x; 1.0547x over previous
#include <cuda_runtime.h>
#include <math.h>

#define N_NODES 12800
#define N_EDGES 128000
#define G 64
#define NPG 200
#define LMD 1024
#define H 128
#define NT 42
#define HOPS 5
#define KT 32
#define ADPAD 66
#define NCHUNK 8         // k_bil split-K factor

// ---------------- static scratch ----------------
__device__ __align__(16) float d_P[(size_t)NCHUNK * H * G * H];  // [ch][k][g][h]
__device__ __align__(16) float d_MT[(size_t)G * H * H];          // [g][h][k]
__device__ __align__(16) float d_nodes[(size_t)N_NODES * H];
__device__ __align__(16) float d_hbuf[(size_t)N_NODES * H];
__device__ __align__(16) float d_hpart[(size_t)2 * N_NODES * H]; // linatt K-halves
__device__ __align__(16) float d_ctx[G * H];
__device__ float d_asrc[N_NODES];
__device__ float d_adst[N_NODES];
__device__ float d_aet[HOPS * NT];
__device__ float d_lscr[N_EDGES];      // fallback logit scratch (deg > 32)
__device__ int d_deg[N_NODES];
__device__ int d_rowptr[N_NODES + 1];
__device__ int d_cursor[N_NODES];
__device__ int d_csr[N_EDGES];         // packed: src | (et << 20)

__device__ __forceinline__ float lrelu(float x) { return x > 0.f ? x : 0.2f * x; }
__device__ __forceinline__ float gelu_exact(float x) {
    return 0.5f * x * (1.f + erff(x * 0.70710678118654752440f));
}

// ---------------- f32x2 packed FMA helpers ----------------
__device__ __forceinline__ unsigned long long pack2(float lo, float hi) {
    unsigned long long r;
    asm("mov.b64 %0, {%1, %2};" : "=l"(r) : "f"(lo), "f"(hi));
    return r;
}
__device__ __forceinline__ void ffma2(unsigned long long& d, unsigned long long a,
                                      unsigned long long b) {
    asm("fma.rn.f32x2 %0, %1, %2, %0;" : "+l"(d) : "l"(a), "l"(b));
}
__device__ __forceinline__ float2 unpack2(unsigned long long v) {
    float2 f;
    asm("mov.b64 {%0, %1}, %2;" : "=f"(f.x), "=f"(f.y) : "l"(v));
    return f;
}

// ---------------- CSR build ----------------
__global__ void k_init() {
    int i = blockIdx.x * blockDim.x + threadIdx.x;
    if (i < N_NODES) d_deg[i] = 0;
}

__global__ void k_count(const int* __restrict__ ei) {
    int e = blockIdx.x * blockDim.x + threadIdx.x;
    if (e < N_EDGES) atomicAdd(&d_deg[ei[N_EDGES + e]], 1);
}

__global__ void k_scan() {
    __shared__ int sums[1024];
    const int CH = 13;
    int t = threadIdx.x;
    int base = t * CH;
    int loc[CH];
    int s = 0;
#pragma unroll
    for (int j = 0; j < CH; j++) {
        int idx = base + j;
        int v = (idx < N_NODES) ? d_deg[idx] : 0;
        loc[j] = v;
        s += v;
    }
    sums[t] = s;
    __syncthreads();
    for (int off = 1; off < 1024; off <<= 1) {
        int v = (t >= off) ? sums[t - off] : 0;
        __syncthreads();
        sums[t] += v;
        __syncthreads();
    }
    int run = (t > 0) ? sums[t - 1] : 0;
#pragma unroll
    for (int j = 0; j < CH; j++) {
        int idx = base + j;
        if (idx < N_NODES) {
            d_rowptr[idx] = run;
            d_cursor[idx] = run;
            run += loc[j];
        }
    }
    if (t == 0) d_rowptr[N_NODES] = N_EDGES;
}

__global__ void k_scatter(const int* __restrict__ ei, const int* __restrict__ et) {
    int e = blockIdx.x * blockDim.x + threadIdx.x;
    if (e < N_EDGES) {
        int d = ei[N_EDGES + e];
        int pos = atomicAdd(&d_cursor[d], 1);
        d_csr[pos] = ei[e] | (et[e] << 20);
    }
}

// ---------------- context embedding ----------------
__global__ void __launch_bounds__(512) k_ctx(const float* __restrict__ lm,
                                             const float* __restrict__ Wlm,
                                             const float* __restrict__ blm) {
    int g = blockIdx.x;
    int t = threadIdx.x;
    int h = t & 127, part = t >> 7;
    const float* lmg = lm + (size_t)g * LMD + part * 256;
    const float* Wp = Wlm + (size_t)(part * 256) * H + h;
    float acc = 0.f;
#pragma unroll 8
    for (int l = 0; l < 256; l++) acc += lmg[l] * Wp[(size_t)l * H];
    __shared__ float red[4][128];
    red[part][h] = acc;
    __syncthreads();
    if (part == 0)
        d_ctx[g * H + h] = red[0][h] + red[1][h] + red[2][h] + red[3][h] + blm[h];
}

// ================= FFMA2 GEMM skeleton =============
#define GEMM_DECL                                         \
    __shared__ unsigned long long AD[KT][ADPAD];          \
    __shared__ float4 WS4[KT][32];                        \
    int t = threadIdx.x;                                  \
    int tx = t & 31, ty = t >> 5;                         \
    int r0 = ty * 8;                                      \
    unsigned long long acc[8][2];                         \
    _Pragma("unroll") for (int r = 0; r < 8; r++) {       \
        acc[r][0] = 0ull; acc[r][1] = 0ull;               \
    }

#define GEMM_COMPUTE                                                        \
    _Pragma("unroll") for (int kk = 0; kk < KT; kk++) {                     \
        ulonglong2 wp = *(const ulonglong2*)&WS4[kk][tx];                   \
        ulonglong2 a0 = *(const ulonglong2*)&AD[kk][r0 + 0];                \
        ulonglong2 a1 = *(const ulonglong2*)&AD[kk][r0 + 2];                \
        ulonglong2 a2 = *(const ulonglong2*)&AD[kk][r0 + 4];                \
        ulonglong2 a3 = *(const ulonglong2*)&AD[kk][r0 + 6];                \
        ffma2(acc[0][0], a0.x, wp.x); ffma2(acc[0][1], a0.x, wp.y);         \
        ffma2(acc[1][0], a0.y, wp.x); ffma2(acc[1][1], a0.y, wp.y);         \
        ffma2(acc[2][0], a1.x, wp.x); ffma2(acc[2][1], a1.x, wp.y);         \
        ffma2(acc[3][0], a1.y, wp.x); ffma2(acc[3][1], a1.y, wp.y);         \
        ffma2(acc[4][0], a2.x, wp.x); ffma2(acc[4][1], a2.x, wp.y);         \
        ffma2(acc[5][0], a2.y, wp.x); ffma2(acc[5][1], a2.y, wp.y);         \
        ffma2(acc[6][0], a3.x, wp.x); ffma2(acc[6][1], a3.x, wp.y);         \
        ffma2(acc[7][0], a3.y, wp.x); ffma2(acc[7][1], a3.y, wp.y);         \
    }

// ---------------- bilinear: M_partial[ch][k][g][h], split-K 8 ----------------
__global__ void __launch_bounds__(256) k_bil(const float* __restrict__ lm,
                                             const float* __restrict__ W) {
    int k = blockIdx.x, ch = blockIdx.y;
    GEMM_DECL
#pragma unroll 1
    for (int tile = 0; tile < 4; tile++) {
        int l0 = ch * 128 + tile * KT;
#pragma unroll
        for (int i = 0; i < 2; i++) {
            int idx4 = t + 256 * i;
            int r = idx4 >> 3, lq = (idx4 & 7) * 4;
            float4 v = *(const float4*)&lm[(size_t)r * LMD + l0 + lq];
            AD[lq + 0][r] = pack2(v.x, v.x);
            AD[lq + 1][r] = pack2(v.y, v.y);
            AD[lq + 2][r] = pack2(v.z, v.z);
            AD[lq + 3][r] = pack2(v.w, v.w);
        }
        const float* Bp = W + ((size_t)k * LMD + l0) * H;
#pragma unroll
        for (int i = 0; i < 4; i++) {
            int idx4 = t + 256 * i;
            int l = idx4 >> 5, q = idx4 & 31;
            WS4[l][q] = *(const float4*)&Bp[(size_t)l * H + q * 4];
        }
        __syncthreads();
        GEMM_COMPUTE
        __syncthreads();
    }
    float* Pp = d_P + ((size_t)(ch * H + k) * G) * H;
#pragma unroll
    for (int r = 0; r < 8; r++) {
        float2 u0 = unpack2(acc[r][0]);
        float2 u1 = unpack2(acc[r][1]);
        *(float4*)&Pp[(size_t)(r0 + r) * H + tx * 4] =
            make_float4(u0.x, u0.y, u1.x, u1.y);
    }
}

// reduce chunks + transpose to MT[g][h][k]
__global__ void k_redT() {
    __shared__ float tile[32][33];
    int g = blockIdx.x, kt = blockIdx.y, ht = blockIdx.z;
    int tx = threadIdx.x, ty = threadIdx.y;
    int k = kt * 32 + ty, h = ht * 32 + tx;
    size_t base = ((size_t)k * G + g) * H + h;
    float s = 0.f;
#pragma unroll
    for (int c = 0; c < NCHUNK; c++) s += d_P[(size_t)c * H * G * H + base];
    tile[ty][tx] = s;
    __syncthreads();
    int h2 = ht * 32 + ty, k2 = kt * 32 + tx;
    d_MT[((size_t)g * H + h2) * H + k2] = tile[tx][ty];
}

// ---------------- nodes init ----------------
__global__ void __launch_bounds__(256) k_nodes0(const float* __restrict__ nemb,
                                                const float* __restrict__ bbil) {
    int g = blockIdx.x, rb = blockIdx.y;
    int row0 = rb * 64;
    GEMM_DECL
    const float* MTg = d_MT + (size_t)g * H * H;
#pragma unroll 1
    for (int tile = 0; tile < 4; tile++) {
        int h0t = tile * KT;
#pragma unroll
        for (int i = 0; i < 2; i++) {
            int idx4 = t + 256 * i;
            int r = idx4 >> 3, lq = (idx4 & 7) * 4;
            int lrow = row0 + r;
            float4 v;
            if (lrow >= NPG) v = make_float4(0.f, 0.f, 0.f, 0.f);
            else if (lrow == 0) v = *(const float4*)&d_ctx[g * H + h0t + lq];
            else v = *(const float4*)&nemb[(size_t)(g * NPG + lrow) * H + h0t + lq];
            AD[lq + 0][r] = pack2(v.x, v.x);
            AD[lq + 1][r] = pack2(v.y, v.y);
            AD[lq + 2][r] = pack2(v.z, v.z);
            AD[lq + 3][r] = pack2(v.w, v.w);
        }
#pragma unroll
        for (int i = 0; i < 4; i++) {
            int idx4 = t + 256 * i;
            int l = idx4 >> 5, q = idx4 & 31;
            WS4[l][q] = *(const float4*)&MTg[(size_t)(h0t + l) * H + q * 4];
        }
        __syncthreads();
        GEMM_COMPUTE
        __syncthreads();
    }
    float4 b4 = *(const float4*)&bbil[tx * 4];
#pragma unroll
    for (int r = 0; r < 8; r++) {
        int lrow = row0 + r0 + r;
        if (lrow < NPG) {
            float2 u0 = unpack2(acc[r][0]);
            float2 u1 = unpack2(acc[r][1]);
            *(float4*)&d_nodes[(size_t)(g * NPG + lrow) * H + tx * 4] =
                make_float4(u0.x + b4.x, u0.y + b4.y, u1.x + b4.z, u1.y + b4.w);
        }
    }
}

// ---------------- per-(hop, edge-type) attention scalar table --------------
__global__ void k_aet(const float* __restrict__ eemb, const float* __restrict__ linE,
                      const float* __restrict__ attE) {
    int i = blockIdx.x / NT, tt = blockIdx.x % NT;
    int c = threadIdx.x;
    const float* le = linE + (size_t)i * H * H;
    const float* em = eemb + (size_t)tt * H;
    float tmp = 0.f;
#pragma unroll 8
    for (int k = 0; k < H; k++) tmp += em[k] * le[(size_t)k * H + c];
    float v = tmp * attE[i * H + c];
    for (int o = 16; o > 0; o >>= 1) v += __shfl_xor_sync(0xffffffffu, v, o);
    __shared__ float ps[4];
    if ((threadIdx.x & 31) == 0) ps[threadIdx.x >> 5] = v;
    __syncthreads();
    if (threadIdx.x == 0) d_aet[i * NT + tt] = ps[0] + ps[1] + ps[2] + ps[3];
}

// ---------------- per-hop: h-partial = nodes @ lin (split-K 2) -------------
__global__ void __launch_bounds__(256) k_lin(const float* __restrict__ lin) {
    int row0 = blockIdx.x * 64;
    int kh = blockIdx.y;
    GEMM_DECL
#pragma unroll 1
    for (int tile = 0; tile < 2; tile++) {
        int k0 = kh * 64 + tile * KT;
#pragma unroll
        for (int i = 0; i < 2; i++) {
            int idx4 = t + 256 * i;
            int r = idx4 >> 3, lq = (idx4 & 7) * 4;
            float4 v = *(const float4*)&d_nodes[(size_t)(row0 + r) * H + k0 + lq];
            AD[lq + 0][r] = pack2(v.x, v.x);
            AD[lq + 1][r] = pack2(v.y, v.y);
            AD[lq + 2][r] = pack2(v.z, v.z);
            AD[lq + 3][r] = pack2(v.w, v.w);
        }
#pragma unroll
        for (int i = 0; i < 4; i++) {
            int idx4 = t + 256 * i;
            int l = idx4 >> 5, q = idx4 & 31;
            WS4[l][q] = *(const float4*)&lin[(size_t)(k0 + l) * H + q * 4];
        }
        __syncthreads();
        GEMM_COMPUTE
        __syncthreads();
    }
    float* Hp = d_hpart + (size_t)kh * N_NODES * H;
#pragma unroll
    for (int r = 0; r < 8; r++) {
        float2 u0 = unpack2(acc[r][0]);
        float2 u1 = unpack2(acc[r][1]);
        *(float4*)&Hp[(size_t)(row0 + r0 + r) * H + tx * 4] =
            make_float4(u0.x, u0.y, u1.x, u1.y);
    }
}

// ---------------- per-hop: combine halves + a_src/a_dst --------------------
__global__ void k_comb(const float* __restrict__ att_s, const float* __restrict__ att_d) {
    int n = blockIdx.x * 8 + (threadIdx.x >> 5);
    int lane = threadIdx.x & 31;
    size_t off = (size_t)n * H + lane * 4;
    float4 a = *(const float4*)&d_hpart[off];
    float4 b = *(const float4*)&d_hpart[(size_t)N_NODES * H + off];
    float4 v = make_float4(a.x + b.x, a.y + b.y, a.z + b.z, a.w + b.w);
    *(float4*)&d_hbuf[off] = v;
    float4 s4 = ((const float4*)att_s)[lane];
    float4 d4 = ((const float4*)att_d)[lane];
    float ps = v.x * s4.x + v.y * s4.y + v.z * s4.z + v.w * s4.w;
    float pd = v.x * d4.x + v.y * d4.y + v.z * d4.z + v.w * d4.w;
#pragma unroll
    for (int o = 16; o > 0; o >>= 1) {
        ps += __shfl_xor_sync(0xffffffffu, ps, o);
        pd += __shfl_xor_sync(0xffffffffu, pd, o);
    }
    if (lane == 0) {
        d_asrc[n] = ps;
        d_adst[n] = pd;
    }
}

// ---------------- per-hop: softmax attention + aggregate + gelu ------------
__global__ void k_gat(int hop, const float* __restrict__ bias) {
    int n = blockIdx.x * 8 + (threadIdx.x >> 5);
    int lane = threadIdx.x & 31;
    const float* aet = d_aet + hop * NT;
    int s0 = d_rowptr[n], s1 = d_rowptr[n + 1];
    int deg = s1 - s0;
    float adn = d_adst[n];
    float asn = d_asrc[n];

    int p_reg = 0;
    float lg_reg = 0.f;
    float m = -1e30f, s = 0.f, aes = 0.f;
    bool fast = (deg <= 32);

    if (fast) {
        if (lane < deg) {
            p_reg = d_csr[s0 + lane];
            float ae = aet[p_reg >> 20];
            lg_reg = lrelu(d_asrc[p_reg & 0xFFFFF] + adn + ae);
            aes = ae;
            m = lg_reg;
            s = 1.f;
        }
    } else {
        for (int e = s0 + lane; e < s1; e += 32) {
            int p = d_csr[e];
            float ae = aet[p >> 20];
            float lg = lrelu(d_asrc[p & 0xFFFFF] + adn + ae);
            d_lscr[e] = lg;
            aes += ae;
            float mn = fmaxf(m, lg);
            s = s * __expf(m - mn) + __expf(lg - mn);
            m = mn;
        }
        __syncwarp();
    }
#pragma unroll
    for (int o = 16; o > 0; o >>= 1) {
        float mo = __shfl_xor_sync(0xffffffffu, m, o);
        float so = __shfl_xor_sync(0xffffffffu, s, o);
        aes += __shfl_xor_sync(0xffffffffu, aes, o);
        float mn = fmaxf(m, mo);
        s = s * __expf(m - mn) + so * __expf(mo - mn);
        m = mn;
    }
    float aloop = aes / (float)(deg > 0 ? deg : 1);
    float slg = lrelu(asn + adn + aloop);
    float mf = fmaxf(m, slg);
    float sf = s * __expf(m - mf) + __expf(slg - mf);
    float inv = 1.f / sf;

    float4 a0 = make_float4(0.f, 0.f, 0.f, 0.f);
    float4 a1 = make_float4(0.f, 0.f, 0.f, 0.f);
    float4 a2 = make_float4(0.f, 0.f, 0.f, 0.f);
    float4 a3 = make_float4(0.f, 0.f, 0.f, 0.f);

    if (fast) {
        // per-lane weight precomputed: serial loop is just shfl + load + fma
        float w_reg = (lane < deg) ? __expf(lg_reg - mf) : 0.f;
        int j = 0;
        for (; j + 4 <= deg; j += 4) {
            int p0 = __shfl_sync(0xffffffffu, p_reg, j);
            int p1 = __shfl_sync(0xffffffffu, p_reg, j + 1);
            int p2 = __shfl_sync(0xffffffffu, p_reg, j + 2);
            int p3 = __shfl_sync(0xffffffffu, p_reg, j + 3);
            float w0 = __shfl_sync(0xffffffffu, w_reg, j);
            float w1 = __shfl_sync(0xffffffffu, w_reg, j + 1);
            float w2 = __shfl_sync(0xffffffffu, w_reg, j + 2);
            float w3 = __shfl_sync(0xffffffffu, w_reg, j + 3);
            float4 h0 = ((const float4*)(d_hbuf + (size_t)(p0 & 0xFFFFF) * H))[lane];
            float4 h1 = ((const float4*)(d_hbuf + (size_t)(p1 & 0xFFFFF) * H))[lane];
            float4 h2 = ((const float4*)(d_hbuf + (size_t)(p2 & 0xFFFFF) * H))[lane];
            float4 h3 = ((const float4*)(d_hbuf + (size_t)(p3 & 0xFFFFF) * H))[lane];
            a0.x += w0 * h0.x; a0.y += w0 * h0.y; a0.z += w0 * h0.z; a0.w += w0 * h0.w;
            a1.x += w1 * h1.x; a1.y += w1 * h1.y; a1.z += w1 * h1.z; a1.w += w1 * h1.w;
            a2.x += w2 * h2.x; a2.y += w2 * h2.y; a2.z += w2 * h2.z; a2.w += w2 * h2.w;
            a3.x += w3 * h3.x; a3.y += w3 * h3.y; a3.z += w3 * h3.z; a3.w += w3 * h3.w;
        }
        for (; j < deg; j++) {
            int p0 = __shfl_sync(0xffffffffu, p_reg, j);
            float w0 = __shfl_sync(0xffffffffu, w_reg, j);
            float4 h0 = ((const float4*)(d_hbuf + (size_t)(p0 & 0xFFFFF) * H))[lane];
            a0.x += w0 * h0.x; a0.y += w0 * h0.y; a0.z += w0 * h0.z; a0.w += w0 * h0.w;
        }
    } else {
        for (int e = s0; e < s1; ++e) {
            int p = d_csr[e];
            float w = __expf(d_lscr[e] - mf);
            float4 hv = ((const float4*)(d_hbuf + (size_t)(p & 0xFFFFF) * H))[lane];
            a0.x += w * hv.x; a0.y += w * hv.y;
            a0.z += w * hv.z; a0.w += w * hv.w;
        }
    }

    float ws = __expf(slg - mf);
    float4 hn = ((const float4*)(d_hbuf + (size_t)n * H))[lane];
    a0.x += a1.x + a2.x + a3.x + ws * hn.x;
    a0.y += a1.y + a2.y + a3.y + ws * hn.y;
    a0.z += a1.z + a2.z + a3.z + ws * hn.z;
    a0.w += a1.w + a2.w + a3.w + ws * hn.w;

    float4 b = ((const float4*)bias)[lane];
    float4 o;
    o.x = gelu_exact(a0.x * inv + b.x);
    o.y = gelu_exact(a0.y * inv + b.y);
    o.z = gelu_exact(a0.z * inv + b.z);
    o.w = gelu_exact(a0.w * inv + b.w);
    ((float4*)(d_nodes + (size_t)n * H))[lane] = o;
}

// ---------------- output gather ----------------
__global__ void k_out(const int* __restrict__ ctxn, float* __restrict__ out) {
    int g = blockIdx.x, k = threadIdx.x;
    out[g * H + k] = d_nodes[(size_t)ctxn[g] * H + k];
}

// ---------------- launch ----------------
extern "C" void kernel_launch(void* const* d_in, const int* in_sizes, int n_in,
                              void* d_out, int out_size) {
    (void)in_sizes; (void)n_in; (void)out_size;
    const float* lm   = (const float*)d_in[0];
    const float* nemb = (const float*)d_in[1];
    const float* Wlm  = (const float*)d_in[2];
    const float* blm  = (const float*)d_in[3];
    const float* Wbil = (const float*)d_in[4];
    const float* bbil = (const float*)d_in[5];
    const float* eemb = (const float*)d_in[6];
    const float* glin = (const float*)d_in[7];
    const float* gas  = (const float*)d_in[8];
    const float* gad  = (const float*)d_in[9];
    const float* gle  = (const float*)d_in[10];
    const float* gae  = (const float*)d_in[11];
    const float* gb   = (const float*)d_in[12];
    const int* ei     = (const int*)d_in[13];
    const int* et     = (const int*)d_in[14];
    const int* ctxn   = (const int*)d_in[16];
    float* out = (float*)d_out;

    // k_bil kept as 4th launch for the ncu capture window
    k_init<<<(N_NODES + 255) / 256, 256>>>();
    k_count<<<(N_EDGES + 255) / 256, 256>>>(ei);
    k_scan<<<1, 1024>>>();
    k_bil<<<dim3(H, NCHUNK), 256>>>(lm, Wbil);
    k_scatter<<<(N_EDGES + 255) / 256, 256>>>(ei, et);
    k_ctx<<<G, 512>>>(lm, Wlm, blm);
    k_redT<<<dim3(G, 4, 4), dim3(32, 32)>>>();
    k_nodes0<<<dim3(G, 4), 256>>>(nemb, bbil);
    k_aet<<<HOPS * NT, 128>>>(eemb, gle, gae);

    for (int hop = 0; hop < HOPS; hop++) {
        k_lin<<<dim3(N_NODES / 64, 2), 256>>>(glin + (size_t)hop * H * H);
        k_comb<<<N_NODES / 8, 256>>>(gas + (size_t)hop * H, gad + (size_t)hop * H);
        k_gat<<<N_NODES / 8, 256>>>(hop, gb + (size_t)hop * H);
    }

    k_out<<<G, 128>>>(ctxn, out);
}

// round 5
// speedup vs baseline: 2.6070x; 1.3664x over previous
#include <cuda_runtime.h>
#include <cuda_bf16.h>
#include <math.h>
#include <stdint.h>

#define N_NODES 12800
#define N_EDGES 128000
#define G 64
#define NPG 200
#define LMD 1024
#define H 128
#define NT 42
#define HOPS 5
#define NCHUNK 8

// smem u32 strides (chosen for conflict-free fragment loads)
#define ASTR 68
#define BSTR 132
#define ASIZE (64 * ASTR)            // 4352 u32
#define BSIZE (64 * BSTR)            // 8448 u32
#define SMEM_BYTES ((2 * ASIZE + 2 * BSIZE) * 4)  // 102400

// ---------------- static scratch ----------------
__device__ __align__(16) float d_P[(size_t)NCHUNK * H * G * H];  // [ch][k][g][h]
__device__ __align__(16) float d_nodes[(size_t)N_NODES * H];
__device__ __align__(16) float d_hbuf[(size_t)N_NODES * H];
__device__ __align__(16) float d_ctx[G * H];
__device__ __align__(16) uint32_t d_lmBig[G * 512];        // lm pairs [g][Lp]
__device__ __align__(16) uint32_t d_lmSml[G * 512];
__device__ __align__(16) uint32_t d_linBig[HOPS * 64 * H]; // [hop][kp][h]
__device__ __align__(16) uint32_t d_linSml[HOPS * 64 * H];
__device__ __align__(16) uint32_t d_MTBig[G * 64 * H];     // [g][hp][k]
__device__ __align__(16) uint32_t d_MTSml[G * 64 * H];
__device__ float d_asrc[N_NODES];
__device__ float d_adst[N_NODES];
__device__ float d_aet[HOPS * NT];
__device__ float d_lscr[N_EDGES];
__device__ int d_deg[N_NODES];
__device__ int d_rowptr[N_NODES + 1];
__device__ int d_cursor[N_NODES];
__device__ int d_csr[N_EDGES];

__device__ __forceinline__ float lrelu(float x) { return x > 0.f ? x : 0.2f * x; }
__device__ __forceinline__ float gelu_exact(float x) {
    return 0.5f * x * (1.f + erff(x * 0.70710678118654752440f));
}

// pack two floats (k-even, k-odd) as bf16x2 (even in low half)
__device__ __forceinline__ uint32_t bpack(float e, float o) {
    __nv_bfloat162 p = __floats2bfloat162_rn(e, o);
    return *reinterpret_cast<uint32_t*>(&p);
}
__device__ __forceinline__ float bbig(float x) {
    return __bfloat162float(__float2bfloat16_rn(x));
}
// produce big/small packed pair for 2 consecutive-k fp32 values
__device__ __forceinline__ void bsplit2(float v0, float v1, uint32_t& big, uint32_t& sml) {
    float b0 = bbig(v0), b1 = bbig(v1);
    big = bpack(b0, b1);
    sml = bpack(v0 - b0, v1 - b1);
}

#define MMA4(C, A0, A1, A2, A3, B0, B1)                                     \
    asm volatile(                                                           \
        "mma.sync.aligned.m16n8k16.row.col.f32.bf16.bf16.f32 "              \
        "{%0,%1,%2,%3}, {%4,%5,%6,%7}, {%8,%9}, {%0,%1,%2,%3};"             \
        : "+f"(C[0]), "+f"(C[1]), "+f"(C[2]), "+f"(C[3])                    \
        : "r"(A0), "r"(A1), "r"(A2), "r"(A3), "r"(B0), "r"(B1));

// one logical-K16 step of the 64x128 tile (3-pass bf16 split)
__device__ __forceinline__ void mma_step(const uint32_t* As_h, const uint32_t* As_l,
                                         const uint32_t* Bs_h, const uint32_t* Bs_l,
                                         float acc[4][2][4], int g, int t, int n0, int ps) {
    uint32_t bh[2][2], bl[2][2];
#pragma unroll
    for (int nt = 0; nt < 2; nt++) {
        int col = n0 + nt * 8 + g;
        bh[nt][0] = Bs_h[(ps + t) * BSTR + col];
        bh[nt][1] = Bs_h[(ps + t + 4) * BSTR + col];
        bl[nt][0] = Bs_l[(ps + t) * BSTR + col];
        bl[nt][1] = Bs_l[(ps + t + 4) * BSTR + col];
    }
#pragma unroll
    for (int mt = 0; mt < 4; mt++) {
        int r0 = (mt * 16 + g) * ASTR, r1 = (mt * 16 + 8 + g) * ASTR;
        uint32_t ah0 = As_h[r0 + ps + t];
        uint32_t ah1 = As_h[r1 + ps + t];
        uint32_t ah2 = As_h[r0 + ps + t + 4];
        uint32_t ah3 = As_h[r1 + ps + t + 4];
        uint32_t al0 = As_l[r0 + ps + t];
        uint32_t al1 = As_l[r1 + ps + t];
        uint32_t al2 = As_l[r0 + ps + t + 4];
        uint32_t al3 = As_l[r1 + ps + t + 4];
#pragma unroll
        for (int nt = 0; nt < 2; nt++) {
            MMA4(acc[mt][nt], ah0, ah1, ah2, ah3, bh[nt][0], bh[nt][1]);
            MMA4(acc[mt][nt], al0, al1, al2, al3, bh[nt][0], bh[nt][1]);
            MMA4(acc[mt][nt], ah0, ah1, ah2, ah3, bl[nt][0], bl[nt][1]);
        }
    }
}

// ---------------- CSR build ----------------
__global__ void k_init() {
    int i = blockIdx.x * blockDim.x + threadIdx.x;
    if (i < N_NODES) d_deg[i] = 0;
}

__global__ void k_count(const int* __restrict__ ei) {
    int e = blockIdx.x * blockDim.x + threadIdx.x;
    if (e < N_EDGES) atomicAdd(&d_deg[ei[N_EDGES + e]], 1);
}

__global__ void k_scan() {
    __shared__ int sums[1024];
    const int CH = 13;
    int t = threadIdx.x;
    int base = t * CH;
    int loc[CH];
    int s = 0;
#pragma unroll
    for (int j = 0; j < CH; j++) {
        int idx = base + j;
        int v = (idx < N_NODES) ? d_deg[idx] : 0;
        loc[j] = v;
        s += v;
    }
    sums[t] = s;
    __syncthreads();
    for (int off = 1; off < 1024; off <<= 1) {
        int v = (t >= off) ? sums[t - off] : 0;
        __syncthreads();
        sums[t] += v;
        __syncthreads();
    }
    int run = (t > 0) ? sums[t - 1] : 0;
#pragma unroll
    for (int j = 0; j < CH; j++) {
        int idx = base + j;
        if (idx < N_NODES) {
            d_rowptr[idx] = run;
            d_cursor[idx] = run;
            run += loc[j];
        }
    }
    if (t == 0) d_rowptr[N_NODES] = N_EDGES;
}

__global__ void k_scatter(const int* __restrict__ ei, const int* __restrict__ et) {
    int e = blockIdx.x * blockDim.x + threadIdx.x;
    if (e < N_EDGES) {
        int d = ei[N_EDGES + e];
        int pos = atomicAdd(&d_cursor[d], 1);
        d_csr[pos] = ei[e] | (et[e] << 20);
    }
}

// ---------------- preconvert lm and lin weights to bf16 pairs --------------
__global__ void k_prep_lm(const float* __restrict__ lm) {
    int id = blockIdx.x * 256 + threadIdx.x;  // 64*512 = 32768
    int r = id >> 9, p = id & 511;
    float2 v = *(const float2*)&lm[(size_t)r * LMD + 2 * p];
    uint32_t b, s;
    bsplit2(v.x, v.y, b, s);
    d_lmBig[r * 512 + p] = b;
    d_lmSml[r * 512 + p] = s;
}

__global__ void k_prep_lin(const float* __restrict__ glin) {
    int id = blockIdx.x * 256 + threadIdx.x;  // 5*64*128 = 40960
    int hop = id >> 13, rem = id & 8191;
    int kp = rem >> 7, h = rem & 127;
    const float* L = glin + (size_t)hop * H * H;
    float v0 = L[(size_t)(2 * kp) * H + h];
    float v1 = L[(size_t)(2 * kp + 1) * H + h];
    uint32_t b, s;
    bsplit2(v0, v1, b, s);
    d_linBig[id] = b;
    d_linSml[id] = s;
}

// ---------------- context embedding ----------------
__global__ void __launch_bounds__(512) k_ctx(const float* __restrict__ lm,
                                             const float* __restrict__ Wlm,
                                             const float* __restrict__ blm) {
    int g = blockIdx.x;
    int t = threadIdx.x;
    int h = t & 127, part = t >> 7;
    const float* lmg = lm + (size_t)g * LMD + part * 256;
    const float* Wp = Wlm + (size_t)(part * 256) * H + h;
    float acc = 0.f;
#pragma unroll 8
    for (int l = 0; l < 256; l++) acc += lmg[l] * Wp[(size_t)l * H];
    __shared__ float red[4][128];
    red[part][h] = acc;
    __syncthreads();
    if (part == 0)
        d_ctx[g * H + h] = red[0][h] + red[1][h] + red[2][h] + red[3][h] + blm[h];
}

// ---------------- bilinear: tensor-core, split-K 8 ----------------
// block (k, ch): C_partial(64g x 128h) = lm[:, chunk] @ W[k][chunk, :]
__global__ void __launch_bounds__(256) k_bil(const float* __restrict__ W) {
    extern __shared__ uint32_t smem_u[];
    uint32_t* As_h = smem_u;
    uint32_t* As_l = smem_u + ASIZE;
    uint32_t* Bs_h = smem_u + 2 * ASIZE;
    uint32_t* Bs_l = smem_u + 2 * ASIZE + BSIZE;
    int k = blockIdx.x, ch = blockIdx.y;
    int tid = threadIdx.x;
    int lane = tid & 31, wid = tid >> 5;
    int g = lane >> 2, t = lane & 3, n0 = wid * 16;

    // A fill: copy preconverted lm pairs (64 rows x 64 pairs)
#pragma unroll
    for (int it = 0; it < 16; it++) {
        int id = tid + 256 * it;
        int r = id >> 6, p = id & 63;
        As_h[r * ASTR + p] = d_lmBig[r * 512 + ch * 64 + p];
        As_l[r * ASTR + p] = d_lmSml[r * 512 + ch * 64 + p];
    }
    // B fill: stream + split W chunk (128 l x 128 h)
    const float* Wb = W + ((size_t)k * LMD + (size_t)ch * 128) * H;
#pragma unroll
    for (int it = 0; it < 8; it++) {
        int id = tid + 256 * it;
        int lp = id >> 5, hq = id & 31;
        float4 v0 = *(const float4*)&Wb[(size_t)(2 * lp) * H + hq * 4];
        float4 v1 = *(const float4*)&Wb[(size_t)(2 * lp + 1) * H + hq * 4];
        uint4 ub, us;
        bsplit2(v0.x, v1.x, ub.x, us.x);
        bsplit2(v0.y, v1.y, ub.y, us.y);
        bsplit2(v0.z, v1.z, ub.z, us.z);
        bsplit2(v0.w, v1.w, ub.w, us.w);
        *(uint4*)&Bs_h[lp * BSTR + hq * 4] = ub;
        *(uint4*)&Bs_l[lp * BSTR + hq * 4] = us;
    }
    __syncthreads();

    float acc[4][2][4];
#pragma unroll
    for (int a = 0; a < 4; a++)
#pragma unroll
        for (int b = 0; b < 2; b++)
#pragma unroll
            for (int c = 0; c < 4; c++) acc[a][b][c] = 0.f;

#pragma unroll
    for (int s = 0; s < 8; s++)
        mma_step(As_h, As_l, Bs_h, Bs_l, acc, g, t, n0, s * 8);

    float* Pp = d_P + ((size_t)(ch * H + k) * G) * H;
#pragma unroll
    for (int mt = 0; mt < 4; mt++) {
        int row = mt * 16 + g;
#pragma unroll
        for (int nt = 0; nt < 2; nt++) {
            int col = n0 + nt * 8 + 2 * t;
            *(float2*)&Pp[(size_t)row * H + col] = make_float2(acc[mt][nt][0], acc[mt][nt][1]);
            *(float2*)&Pp[(size_t)(row + 8) * H + col] = make_float2(acc[mt][nt][2], acc[mt][nt][3]);
        }
    }
}

// reduce chunks + transpose + split to MT bf16 pairs [g][hp][k]
__global__ void k_redT() {
    __shared__ float tile[32][33];
    int g = blockIdx.x, kt = blockIdx.y, ht = blockIdx.z;
    int tx = threadIdx.x, ty = threadIdx.y;
    int k = kt * 32 + ty, h = ht * 32 + tx;
    size_t base = ((size_t)k * G + g) * H + h;
    float s = 0.f;
#pragma unroll
    for (int c = 0; c < NCHUNK; c++) s += d_P[(size_t)c * H * G * H + base];
    tile[ty][tx] = s;  // tile[k_local][h_local]
    __syncthreads();
    if (ty < 16) {
        float v0 = tile[tx][2 * ty];      // (k_local=tx, h_local=2ty)
        float v1 = tile[tx][2 * ty + 1];
        uint32_t b, sm;
        bsplit2(v0, v1, b, sm);
        int idx = (g * 64 + ht * 16 + ty) * H + kt * 32 + tx;
        d_MTBig[idx] = b;
        d_MTSml[idx] = sm;
    }
}

// ---------------- nodes init: tensor-core ----------------
__global__ void __launch_bounds__(256) k_nodes0(const float* __restrict__ nemb,
                                                const float* __restrict__ bbil) {
    extern __shared__ uint32_t smem_u[];
    uint32_t* As_h = smem_u;
    uint32_t* As_l = smem_u + ASIZE;
    uint32_t* Bs_h = smem_u + 2 * ASIZE;
    uint32_t* Bs_l = smem_u + 2 * ASIZE + BSIZE;
    int gph = blockIdx.x, rb = blockIdx.y;
    int row0 = rb * 64;
    int tid = threadIdx.x;
    int lane = tid & 31, wid = tid >> 5;
    int g = lane >> 2, t = lane & 3, n0 = wid * 16;

    // A fill: x2 rows (ctx substitution), split in-block
#pragma unroll
    for (int it = 0; it < 16; it++) {
        int id = tid + 256 * it;
        int r = id >> 6, kp = id & 63;
        int lrow = row0 + r;
        float2 v;
        if (lrow >= NPG) v = make_float2(0.f, 0.f);
        else if (lrow == 0) v = *(const float2*)&d_ctx[gph * H + 2 * kp];
        else v = *(const float2*)&nemb[(size_t)(gph * NPG + lrow) * H + 2 * kp];
        uint32_t b, s;
        bsplit2(v.x, v.y, b, s);
        As_h[r * ASTR + kp] = b;
        As_l[r * ASTR + kp] = s;
    }
    // B fill: copy MT pairs
    const uint32_t* MB = d_MTBig + gph * 64 * H;
    const uint32_t* MS = d_MTSml + gph * 64 * H;
#pragma unroll
    for (int it = 0; it < 8; it++) {
        int id = tid + 256 * it;
        int hp = id >> 5, q = id & 31;
        *(uint4*)&Bs_h[hp * BSTR + q * 4] = *(const uint4*)&MB[hp * H + q * 4];
        *(uint4*)&Bs_l[hp * BSTR + q * 4] = *(const uint4*)&MS[hp * H + q * 4];
    }
    __syncthreads();

    float acc[4][2][4];
#pragma unroll
    for (int a = 0; a < 4; a++)
#pragma unroll
        for (int b = 0; b < 2; b++)
#pragma unroll
            for (int c = 0; c < 4; c++) acc[a][b][c] = 0.f;

#pragma unroll
    for (int s = 0; s < 8; s++)
        mma_step(As_h, As_l, Bs_h, Bs_l, acc, g, t, n0, s * 8);

#pragma unroll
    for (int mt = 0; mt < 4; mt++) {
#pragma unroll
        for (int nt = 0; nt < 2; nt++) {
            int col = n0 + nt * 8 + 2 * t;
            float b0 = bbil[col], b1 = bbil[col + 1];
            int lr0 = row0 + mt * 16 + g;
            if (lr0 < NPG)
                *(float2*)&d_nodes[(size_t)(gph * NPG + lr0) * H + col] =
                    make_float2(acc[mt][nt][0] + b0, acc[mt][nt][1] + b1);
            int lr1 = lr0 + 8;
            if (lr1 < NPG)
                *(float2*)&d_nodes[(size_t)(gph * NPG + lr1) * H + col] =
                    make_float2(acc[mt][nt][2] + b0, acc[mt][nt][3] + b1);
        }
    }
}

// ---------------- per-(hop, edge-type) attention scalar table --------------
__global__ void k_aet(const float* __restrict__ eemb, const float* __restrict__ linE,
                      const float* __restrict__ attE) {
    int i = blockIdx.x / NT, tt = blockIdx.x % NT;
    int c = threadIdx.x;
    const float* le = linE + (size_t)i * H * H;
    const float* em = eemb + (size_t)tt * H;
    float tmp = 0.f;
#pragma unroll 8
    for (int k = 0; k < H; k++) tmp += em[k] * le[(size_t)k * H + c];
    float v = tmp * attE[i * H + c];
    for (int o = 16; o > 0; o >>= 1) v += __shfl_xor_sync(0xffffffffu, v, o);
    __shared__ float ps[4];
    if ((threadIdx.x & 31) == 0) ps[threadIdx.x >> 5] = v;
    __syncthreads();
    if (threadIdx.x == 0) d_aet[i * NT + tt] = ps[0] + ps[1] + ps[2] + ps[3];
}

// ---------------- per-hop: h = nodes @ lin (tensor), fused a_src/a_dst -----
__global__ void __launch_bounds__(256) k_lin(int hop, const float* __restrict__ att_s,
                                             const float* __restrict__ att_d) {
    extern __shared__ uint32_t smem_u[];
    uint32_t* As_h = smem_u;
    uint32_t* As_l = smem_u + ASIZE;
    uint32_t* Bs_h = smem_u + 2 * ASIZE;
    uint32_t* Bs_l = smem_u + 2 * ASIZE + BSIZE;
    int row0 = blockIdx.x * 64;
    int tid = threadIdx.x;
    int lane = tid & 31, wid = tid >> 5;
    int g = lane >> 2, t = lane & 3, n0 = wid * 16;

#pragma unroll
    for (int it = 0; it < 16; it++) {
        int id = tid + 256 * it;
        int r = id >> 6, kp = id & 63;
        float2 v = *(const float2*)&d_nodes[(size_t)(row0 + r) * H + 2 * kp];
        uint32_t b, s;
        bsplit2(v.x, v.y, b, s);
        As_h[r * ASTR + kp] = b;
        As_l[r * ASTR + kp] = s;
    }
    const uint32_t* LB = d_linBig + hop * 64 * H;
    const uint32_t* LS = d_linSml + hop * 64 * H;
#pragma unroll
    for (int it = 0; it < 8; it++) {
        int id = tid + 256 * it;
        int kp = id >> 5, q = id & 31;
        *(uint4*)&Bs_h[kp * BSTR + q * 4] = *(const uint4*)&LB[kp * H + q * 4];
        *(uint4*)&Bs_l[kp * BSTR + q * 4] = *(const uint4*)&LS[kp * H + q * 4];
    }
    __syncthreads();

    float acc[4][2][4];
#pragma unroll
    for (int a = 0; a < 4; a++)
#pragma unroll
        for (int b = 0; b < 2; b++)
#pragma unroll
            for (int c = 0; c < 4; c++) acc[a][b][c] = 0.f;

#pragma unroll
    for (int s = 0; s < 8; s++)
        mma_step(As_h, As_l, Bs_h, Bs_l, acc, g, t, n0, s * 8);

    // write hbuf
#pragma unroll
    for (int mt = 0; mt < 4; mt++) {
        int row = row0 + mt * 16 + g;
#pragma unroll
        for (int nt = 0; nt < 2; nt++) {
            int col = n0 + nt * 8 + 2 * t;
            *(float2*)&d_hbuf[(size_t)row * H + col] = make_float2(acc[mt][nt][0], acc[mt][nt][1]);
            *(float2*)&d_hbuf[(size_t)(row + 8) * H + col] = make_float2(acc[mt][nt][2], acc[mt][nt][3]);
        }
    }

    // fused a_src/a_dst: per-thread partial dots over owned columns
    float pS[4][2] = {{0.f, 0.f}, {0.f, 0.f}, {0.f, 0.f}, {0.f, 0.f}};
    float pD[4][2] = {{0.f, 0.f}, {0.f, 0.f}, {0.f, 0.f}, {0.f, 0.f}};
#pragma unroll
    for (int nt = 0; nt < 2; nt++) {
        int c0 = n0 + nt * 8 + 2 * t;
        float as0 = att_s[c0], as1 = att_s[c0 + 1];
        float ad0 = att_d[c0], ad1 = att_d[c0 + 1];
#pragma unroll
        for (int mt = 0; mt < 4; mt++) {
            pS[mt][0] += acc[mt][nt][0] * as0 + acc[mt][nt][1] * as1;
            pS[mt][1] += acc[mt][nt][2] * as0 + acc[mt][nt][3] * as1;
            pD[mt][0] += acc[mt][nt][0] * ad0 + acc[mt][nt][1] * ad1;
            pD[mt][1] += acc[mt][nt][2] * ad0 + acc[mt][nt][3] * ad1;
        }
    }
#pragma unroll
    for (int o = 1; o < 4; o <<= 1) {
#pragma unroll
        for (int mt = 0; mt < 4; mt++) {
#pragma unroll
            for (int hf = 0; hf < 2; hf++) {
                pS[mt][hf] += __shfl_xor_sync(0xffffffffu, pS[mt][hf], o);
                pD[mt][hf] += __shfl_xor_sync(0xffffffffu, pD[mt][hf], o);
            }
        }
    }
    __syncthreads();  // done reading As/Bs; reuse smem
    float* sS = (float*)smem_u;        // [8][64]
    float* sD = (float*)smem_u + 512;
    if (t == 0) {
#pragma unroll
        for (int mt = 0; mt < 4; mt++) {
#pragma unroll
            for (int hf = 0; hf < 2; hf++) {
                int row = mt * 16 + hf * 8 + g;
                sS[wid * 64 + row] = pS[mt][hf];
                sD[wid * 64 + row] = pD[mt][hf];
            }
        }
    }
    __syncthreads();
    if (tid < 128) {
        int which = tid >> 6, row = tid & 63;
        const float* sp = which ? sD : sS;
        float s = 0.f;
#pragma unroll
        for (int w = 0; w < 8; w++) s += sp[w * 64 + row];
        if (which) d_adst[row0 + row] = s;
        else d_asrc[row0 + row] = s;
    }
}

// ---------------- per-hop: softmax attention + aggregate + gelu ------------
__global__ void k_gat(int hop, const float* __restrict__ bias) {
    int n = blockIdx.x * 8 + (threadIdx.x >> 5);
    int lane = threadIdx.x & 31;
    const float* aet = d_aet + hop * NT;
    int s0 = d_rowptr[n], s1 = d_rowptr[n + 1];
    int deg = s1 - s0;
    float adn = d_adst[n];
    float asn = d_asrc[n];

    int p_reg = 0;
    float lg_reg = 0.f;
    float m = -1e30f, s = 0.f, aes = 0.f;
    bool fast = (deg <= 32);

    if (fast) {
        if (lane < deg) {
            p_reg = d_csr[s0 + lane];
            float ae = aet[p_reg >> 20];
            lg_reg = lrelu(d_asrc[p_reg & 0xFFFFF] + adn + ae);
            aes = ae;
            m = lg_reg;
            s = 1.f;
        }
    } else {
        for (int e = s0 + lane; e < s1; e += 32) {
            int p = d_csr[e];
            float ae = aet[p >> 20];
            float lg = lrelu(d_asrc[p & 0xFFFFF] + adn + ae);
            d_lscr[e] = lg;
            aes += ae;
            float mn = fmaxf(m, lg);
            s = s * __expf(m - mn) + __expf(lg - mn);
            m = mn;
        }
        __syncwarp();
    }
#pragma unroll
    for (int o = 16; o > 0; o >>= 1) {
        float mo = __shfl_xor_sync(0xffffffffu, m, o);
        float so = __shfl_xor_sync(0xffffffffu, s, o);
        aes += __shfl_xor_sync(0xffffffffu, aes, o);
        float mn = fmaxf(m, mo);
        s = s * __expf(m - mn) + so * __expf(mo - mn);
        m = mn;
    }
    float aloop = aes / (float)(deg > 0 ? deg : 1);
    float slg = lrelu(asn + adn + aloop);
    float mf = fmaxf(m, slg);
    float sf = s * __expf(m - mf) + __expf(slg - mf);
    float inv = 1.f / sf;

    float4 a0 = make_float4(0.f, 0.f, 0.f, 0.f);
    float4 a1 = make_float4(0.f, 0.f, 0.f, 0.f);
    float4 a2 = make_float4(0.f, 0.f, 0.f, 0.f);
    float4 a3 = make_float4(0.f, 0.f, 0.f, 0.f);

    if (fast) {
        float w_reg = (lane < deg) ? __expf(lg_reg - mf) : 0.f;
        int j = 0;
        for (; j + 4 <= deg; j += 4) {
            int p0 = __shfl_sync(0xffffffffu, p_reg, j);
            int p1 = __shfl_sync(0xffffffffu, p_reg, j + 1);
            int p2 = __shfl_sync(0xffffffffu, p_reg, j + 2);
            int p3 = __shfl_sync(0xffffffffu, p_reg, j + 3);
            float w0 = __shfl_sync(0xffffffffu, w_reg, j);
            float w1 = __shfl_sync(0xffffffffu, w_reg, j + 1);
            float w2 = __shfl_sync(0xffffffffu, w_reg, j + 2);
            float w3 = __shfl_sync(0xffffffffu, w_reg, j + 3);
            float4 h0 = ((const float4*)(d_hbuf + (size_t)(p0 & 0xFFFFF) * H))[lane];
            float4 h1 = ((const float4*)(d_hbuf + (size_t)(p1 & 0xFFFFF) * H))[lane];
            float4 h2 = ((const float4*)(d_hbuf + (size_t)(p2 & 0xFFFFF) * H))[lane];
            float4 h3 = ((const float4*)(d_hbuf + (size_t)(p3 & 0xFFFFF) * H))[lane];
            a0.x += w0 * h0.x; a0.y += w0 * h0.y; a0.z += w0 * h0.z; a0.w += w0 * h0.w;
            a1.x += w1 * h1.x; a1.y += w1 * h1.y; a1.z += w1 * h1.z; a1.w += w1 * h1.w;
            a2.x += w2 * h2.x; a2.y += w2 * h2.y; a2.z += w2 * h2.z; a2.w += w2 * h2.w;
            a3.x += w3 * h3.x; a3.y += w3 * h3.y; a3.z += w3 * h3.z; a3.w += w3 * h3.w;
        }
        for (; j < deg; j++) {
            int p0 = __shfl_sync(0xffffffffu, p_reg, j);
            float w0 = __shfl_sync(0xffffffffu, w_reg, j);
            float4 h0 = ((const float4*)(d_hbuf + (size_t)(p0 & 0xFFFFF) * H))[lane];
            a0.x += w0 * h0.x; a0.y += w0 * h0.y; a0.z += w0 * h0.z; a0.w += w0 * h0.w;
        }
    } else {
        for (int e = s0; e < s1; ++e) {
            int p = d_csr[e];
            float w = __expf(d_lscr[e] - mf);
            float4 hv = ((const float4*)(d_hbuf + (size_t)(p & 0xFFFFF) * H))[lane];
            a0.x += w * hv.x; a0.y += w * hv.y;
            a0.z += w * hv.z; a0.w += w * hv.w;
        }
    }

    float ws = __expf(slg - mf);
    float4 hn = ((const float4*)(d_hbuf + (size_t)n * H))[lane];
    a0.x += a1.x + a2.x + a3.x + ws * hn.x;
    a0.y += a1.y + a2.y + a3.y + ws * hn.y;
    a0.z += a1.z + a2.z + a3.z + ws * hn.z;
    a0.w += a1.w + a2.w + a3.w + ws * hn.w;

    float4 b = ((const float4*)bias)[lane];
    float4 o;
    o.x = gelu_exact(a0.x * inv + b.x);
    o.y = gelu_exact(a0.y * inv + b.y);
    o.z = gelu_exact(a0.z * inv + b.z);
    o.w = gelu_exact(a0.w * inv + b.w);
    ((float4*)(d_nodes + (size_t)n * H))[lane] = o;
}

// ---------------- output gather ----------------
__global__ void k_out(const int* __restrict__ ctxn, float* __restrict__ out) {
    int g = blockIdx.x, k = threadIdx.x;
    out[g * H + k] = d_nodes[(size_t)ctxn[g] * H + k];
}

// ---------------- launch ----------------
extern "C" void kernel_launch(void* const* d_in, const int* in_sizes, int n_in,
                              void* d_out, int out_size) {
    (void)in_sizes; (void)n_in; (void)out_size;
    const float* lm   = (const float*)d_in[0];
    const float* nemb = (const float*)d_in[1];
    const float* Wlm  = (const float*)d_in[2];
    const float* blm  = (const float*)d_in[3];
    const float* Wbil = (const float*)d_in[4];
    const float* bbil = (const float*)d_in[5];
    const float* eemb = (const float*)d_in[6];
    const float* glin = (const float*)d_in[7];
    const float* gas  = (const float*)d_in[8];
    const float* gad  = (const float*)d_in[9];
    const float* gle  = (const float*)d_in[10];
    const float* gae  = (const float*)d_in[11];
    const float* gb   = (const float*)d_in[12];
    const int* ei     = (const int*)d_in[13];
    const int* et     = (const int*)d_in[14];
    const int* ctxn   = (const int*)d_in[16];
    float* out = (float*)d_out;

    // idempotent, not a stream op, not an allocation — capture-safe
    cudaFuncSetAttribute(k_bil, cudaFuncAttributeMaxDynamicSharedMemorySize, SMEM_BYTES);
    cudaFuncSetAttribute(k_nodes0, cudaFuncAttributeMaxDynamicSharedMemorySize, SMEM_BYTES);
    cudaFuncSetAttribute(k_lin, cudaFuncAttributeMaxDynamicSharedMemorySize, SMEM_BYTES);

    // k_bil kept as 4th launch for the ncu capture window
    k_prep_lm<<<128, 256>>>(lm);
    k_init<<<(N_NODES + 255) / 256, 256>>>();
    k_count<<<(N_EDGES + 255) / 256, 256>>>(ei);
    k_bil<<<dim3(H, NCHUNK), 256, SMEM_BYTES>>>(Wbil);
    k_scan<<<1, 1024>>>();
    k_scatter<<<(N_EDGES + 255) / 256, 256>>>(ei, et);
    k_ctx<<<G, 512>>>(lm, Wlm, blm);
    k_prep_lin<<<160, 256>>>(glin);
    k_redT<<<dim3(G, 4, 4), dim3(32, 32)>>>();
    k_nodes0<<<dim3(G, 4), 256, SMEM_BYTES>>>(nemb, bbil);
    k_aet<<<HOPS * NT, 128>>>(eemb, gle, gae);

    for (int hop = 0; hop < HOPS; hop++) {
        k_lin<<<N_NODES / 64, 256, SMEM_BYTES>>>(hop, gas + (size_t)hop * H,
                                                 gad + (size_t)hop * H);
        k_gat<<<N_NODES / 8, 256>>>(hop, gb + (size_t)hop * H);
    }

    k_out<<<G, 128>>>(ctxn, out);
}

// round 6
// speedup vs baseline: 2.8364x; 1.0880x over previous
#include <cuda_runtime.h>
#include <cuda_bf16.h>
#include <math.h>
#include <stdint.h>

#define N_NODES 12800
#define N_EDGES 128000
#define G 64
#define NPG 200
#define LMD 1024
#define H 128
#define NT 42
#define HOPS 5
#define NCH4 4                 // k_bil split-K factor
#define CHL (LMD / NCH4)       // 256 L per chunk = 128 pairs = 16 k16-steps

// ---- k_bil smem (new layout) ----
#define AFRAG (16 * 4 * 32 * 4)      // 8192 u32, fragment-major A
#define RSTR 132                     // raw B row stride (f32 words)
#define RSTAGE (16 * RSTR)           // 2112 u32 per stage
#define NSTAGE 3
#define BIL_SMEM ((2 * AFRAG + NSTAGE * RSTAGE) * 4)   // 90880 B

// ---- k_nodes0 / k_lin smem (R5 layout) ----
#define ASTR 68
#define BSTR 132
#define ASIZE (64 * ASTR)
#define BSIZE (64 * BSTR)
#define SMEM_BYTES ((2 * ASIZE + 2 * BSIZE) * 4)  // 102400

// ---------------- static scratch ----------------
__device__ __align__(16) float d_P[(size_t)NCH4 * H * G * H];   // [ch][k][g][h]
__device__ __align__(16) float d_Pc[(size_t)NCH4 * G * H];      // ctx partials
__device__ __align__(16) float d_nodes[(size_t)N_NODES * H];
__device__ __align__(16) float d_hbuf[(size_t)N_NODES * H];
__device__ __align__(16) uint32_t d_lmBig[G * 512];
__device__ __align__(16) uint32_t d_lmSml[G * 512];
__device__ __align__(16) uint32_t d_linBig[HOPS * 64 * H];
__device__ __align__(16) uint32_t d_linSml[HOPS * 64 * H];
__device__ __align__(16) uint32_t d_MTBig[G * 64 * H];
__device__ __align__(16) uint32_t d_MTSml[G * 64 * H];
__device__ float d_asrc[N_NODES];
__device__ float d_adst[N_NODES];
__device__ float d_aet[HOPS * NT];
__device__ float d_lscr[N_EDGES];
__device__ int d_deg[N_NODES];
__device__ int d_rowptr[N_NODES + 1];
__device__ int d_cursor[N_NODES];
__device__ int d_csr[N_EDGES];

__device__ __forceinline__ float lrelu(float x) { return x > 0.f ? x : 0.2f * x; }
__device__ __forceinline__ float gelu_exact(float x) {
    return 0.5f * x * (1.f + erff(x * 0.70710678118654752440f));
}

__device__ __forceinline__ uint32_t bpack(float e, float o) {
    __nv_bfloat162 p = __floats2bfloat162_rn(e, o);
    return *reinterpret_cast<uint32_t*>(&p);
}
__device__ __forceinline__ float bbig(float x) {
    return __bfloat162float(__float2bfloat16_rn(x));
}
__device__ __forceinline__ void bsplit2(float v0, float v1, uint32_t& big, uint32_t& sml) {
    float b0 = bbig(v0), b1 = bbig(v1);
    big = bpack(b0, b1);
    sml = bpack(v0 - b0, v1 - b1);
}

__device__ __forceinline__ void cp16(uint32_t saddr, const void* gptr) {
    asm volatile("cp.async.ca.shared.global [%0], [%1], 16;" :: "r"(saddr), "l"(gptr));
}
__device__ __forceinline__ void cp_commit() { asm volatile("cp.async.commit_group;"); }
__device__ __forceinline__ void cp_wait1() { asm volatile("cp.async.wait_group 1;"); }

#define MMA4(C, A0, A1, A2, A3, B0, B1)                                     \
    asm volatile(                                                           \
        "mma.sync.aligned.m16n8k16.row.col.f32.bf16.bf16.f32 "              \
        "{%0,%1,%2,%3}, {%4,%5,%6,%7}, {%8,%9}, {%0,%1,%2,%3};"             \
        : "+f"(C[0]), "+f"(C[1]), "+f"(C[2]), "+f"(C[3])                    \
        : "r"(A0), "r"(A1), "r"(A2), "r"(A3), "r"(B0), "r"(B1));

// one K16 step with array-layout A/B (k_nodes0 / k_lin)
__device__ __forceinline__ void mma_step(const uint32_t* As_h, const uint32_t* As_l,
                                         const uint32_t* Bs_h, const uint32_t* Bs_l,
                                         float acc[4][2][4], int g, int t, int n0, int ps) {
    uint32_t bh[2][2], bl[2][2];
#pragma unroll
    for (int nt = 0; nt < 2; nt++) {
        int col = n0 + nt * 8 + g;
        bh[nt][0] = Bs_h[(ps + t) * BSTR + col];
        bh[nt][1] = Bs_h[(ps + t + 4) * BSTR + col];
        bl[nt][0] = Bs_l[(ps + t) * BSTR + col];
        bl[nt][1] = Bs_l[(ps + t + 4) * BSTR + col];
    }
#pragma unroll
    for (int mt = 0; mt < 4; mt++) {
        int r0 = (mt * 16 + g) * ASTR, r1 = (mt * 16 + 8 + g) * ASTR;
        uint32_t ah0 = As_h[r0 + ps + t];
        uint32_t ah1 = As_h[r1 + ps + t];
        uint32_t ah2 = As_h[r0 + ps + t + 4];
        uint32_t ah3 = As_h[r1 + ps + t + 4];
        uint32_t al0 = As_l[r0 + ps + t];
        uint32_t al1 = As_l[r1 + ps + t];
        uint32_t al2 = As_l[r0 + ps + t + 4];
        uint32_t al3 = As_l[r1 + ps + t + 4];
#pragma unroll
        for (int nt = 0; nt < 2; nt++) {
            MMA4(acc[mt][nt], ah0, ah1, ah2, ah3, bh[nt][0], bh[nt][1]);
            MMA4(acc[mt][nt], al0, al1, al2, al3, bh[nt][0], bh[nt][1]);
            MMA4(acc[mt][nt], ah0, ah1, ah2, ah3, bl[nt][0], bl[nt][1]);
        }
    }
}

// ---------------- CSR build ----------------
__global__ void k_init() {
    int i = blockIdx.x * blockDim.x + threadIdx.x;
    if (i < N_NODES) d_deg[i] = 0;
}

__global__ void k_count(const int* __restrict__ ei) {
    int e = blockIdx.x * blockDim.x + threadIdx.x;
    if (e < N_EDGES) atomicAdd(&d_deg[ei[N_EDGES + e]], 1);
}

__global__ void k_scan() {
    __shared__ int sums[1024];
    const int CH = 13;
    int t = threadIdx.x;
    int base = t * CH;
    int loc[CH];
    int s = 0;
#pragma unroll
    for (int j = 0; j < CH; j++) {
        int idx = base + j;
        int v = (idx < N_NODES) ? d_deg[idx] : 0;
        loc[j] = v;
        s += v;
    }
    sums[t] = s;
    __syncthreads();
    for (int off = 1; off < 1024; off <<= 1) {
        int v = (t >= off) ? sums[t - off] : 0;
        __syncthreads();
        sums[t] += v;
        __syncthreads();
    }
    int run = (t > 0) ? sums[t - 1] : 0;
#pragma unroll
    for (int j = 0; j < CH; j++) {
        int idx = base + j;
        if (idx < N_NODES) {
            d_rowptr[idx] = run;
            d_cursor[idx] = run;
            run += loc[j];
        }
    }
    if (t == 0) d_rowptr[N_NODES] = N_EDGES;
}

__global__ void k_scatter(const int* __restrict__ ei, const int* __restrict__ et) {
    int e = blockIdx.x * blockDim.x + threadIdx.x;
    if (e < N_EDGES) {
        int d = ei[N_EDGES + e];
        int pos = atomicAdd(&d_cursor[d], 1);
        d_csr[pos] = ei[e] | (et[e] << 20);
    }
}

// ---------------- preconvert lm and lin weights to bf16 pairs --------------
__global__ void k_prep_lm(const float* __restrict__ lm) {
    int id = blockIdx.x * 256 + threadIdx.x;
    int r = id >> 9, p = id & 511;
    float2 v = *(const float2*)&lm[(size_t)r * LMD + 2 * p];
    uint32_t b, s;
    bsplit2(v.x, v.y, b, s);
    d_lmBig[r * 512 + p] = b;
    d_lmSml[r * 512 + p] = s;
}

__global__ void k_prep_lin(const float* __restrict__ glin) {
    int id = blockIdx.x * 256 + threadIdx.x;
    int hop = id >> 13, rem = id & 8191;
    int kp = rem >> 7, h = rem & 127;
    const float* L = glin + (size_t)hop * H * H;
    float v0 = L[(size_t)(2 * kp) * H + h];
    float v1 = L[(size_t)(2 * kp + 1) * H + h];
    uint32_t b, s;
    bsplit2(v0, v1, b, s);
    d_linBig[id] = b;
    d_linSml[id] = s;
}

// ---------------- bilinear + ctx: pipelined tensor-core ----------------
// block (k, ch): k<128 -> W_bil slice k; k==128 -> W_lm (ctx GEMM).
// C_partial(64g x 128h) = lm[:, chunk] @ B[chunk, :]
__global__ void __launch_bounds__(256) k_bil(const float* __restrict__ W,
                                             const float* __restrict__ Wlm) {
    extern __shared__ uint32_t su[];
    uint32_t* Af_h = su;                    // fragment-major A (big)
    uint32_t* Af_l = su + AFRAG;            // (small)
    float* raw = (float*)(su + 2 * AFRAG);  // NSTAGE stages of raw fp32 B
    uint32_t raw_s = (uint32_t)__cvta_generic_to_shared(raw);

    int k = blockIdx.x, ch = blockIdx.y;
    int tid = threadIdx.x;
    int lane = tid & 31, wid = tid >> 5;
    int g = lane >> 2, t = lane & 3, n0 = wid * 16;

    const float* Bg = (k < H) ? (W + ((size_t)k * LMD + (size_t)ch * CHL) * H)
                              : (Wlm + (size_t)(ch * CHL) * H);

    // prologue: issue stages 0,1
#pragma unroll
    for (int s = 0; s < NSTAGE - 1; s++) {
#pragma unroll
        for (int i = 0; i < 2; i++) {
            int id = tid + 256 * i;
            int row = id >> 5, c4 = id & 31;
            cp16(raw_s + (s * RSTAGE + row * RSTR + c4 * 4) * 4,
                 Bg + (size_t)(s * 16 + row) * H + c4 * 4);
        }
        cp_commit();
    }

    // A fill: fragment-major from preconverted lm pairs
#pragma unroll
    for (int it = 0; it < 32; it++) {
        int id = tid + 256 * it;
        int r = id >> 7, p = id & 127;
        int step = p >> 3, tt = p & 3, h4 = (p >> 2) & 1;
        int gg = r & 7, hb = (r >> 3) & 1, mt = r >> 4;
        int slot = ((step * 4 + mt) * 32 + gg * 4 + tt) * 4 + h4 * 2 + hb;
        Af_h[slot] = d_lmBig[r * 512 + ch * 128 + p];
        Af_l[slot] = d_lmSml[r * 512 + ch * 128 + p];
    }

    float acc[4][2][4];
#pragma unroll
    for (int a = 0; a < 4; a++)
#pragma unroll
        for (int b = 0; b < 2; b++)
#pragma unroll
            for (int c = 0; c < 4; c++) acc[a][b][c] = 0.f;

#pragma unroll 1
    for (int step = 0; step < 16; step++) {
        cp_wait1();
        __syncthreads();
        // issue stage step+2 into buffer (step+2)%3 (read finished at step-1)
        if (step + NSTAGE - 1 < 16) {
            int s = step + NSTAGE - 1;
            int buf = s % NSTAGE;
#pragma unroll
            for (int i = 0; i < 2; i++) {
                int id = tid + 256 * i;
                int row = id >> 5, c4 = id & 31;
                cp16(raw_s + (buf * RSTAGE + row * RSTR + c4 * 4) * 4,
                     Bg + (size_t)(s * 16 + row) * H + c4 * 4);
            }
        }
        cp_commit();

        const float* rb = raw + (step % NSTAGE) * RSTAGE;
        uint32_t bh[2][2], bl[2][2];
#pragma unroll
        for (int nt = 0; nt < 2; nt++) {
            int col = n0 + nt * 8 + g;
            bsplit2(rb[(2 * t) * RSTR + col], rb[(2 * t + 1) * RSTR + col],
                    bh[nt][0], bl[nt][0]);
            bsplit2(rb[(2 * t + 8) * RSTR + col], rb[(2 * t + 9) * RSTR + col],
                    bh[nt][1], bl[nt][1]);
        }
#pragma unroll
        for (int mt = 0; mt < 4; mt++) {
            uint4 ah = *(const uint4*)&Af_h[((step * 4 + mt) * 32 + lane) * 4];
            uint4 al = *(const uint4*)&Af_l[((step * 4 + mt) * 32 + lane) * 4];
#pragma unroll
            for (int nt = 0; nt < 2; nt++) {
                MMA4(acc[mt][nt], ah.x, ah.y, ah.z, ah.w, bh[nt][0], bh[nt][1]);
                MMA4(acc[mt][nt], al.x, al.y, al.z, al.w, bh[nt][0], bh[nt][1]);
                MMA4(acc[mt][nt], ah.x, ah.y, ah.z, ah.w, bl[nt][0], bl[nt][1]);
            }
        }
        __syncthreads();
    }

    float* Pp = (k < H) ? (d_P + ((size_t)(ch * H + k) * G) * H)
                        : (d_Pc + (size_t)ch * G * H);
#pragma unroll
    for (int mt = 0; mt < 4; mt++) {
        int row = mt * 16 + g;
#pragma unroll
        for (int nt = 0; nt < 2; nt++) {
            int col = n0 + nt * 8 + 2 * t;
            *(float2*)&Pp[(size_t)row * H + col] = make_float2(acc[mt][nt][0], acc[mt][nt][1]);
            *(float2*)&Pp[(size_t)(row + 8) * H + col] = make_float2(acc[mt][nt][2], acc[mt][nt][3]);
        }
    }
}

// reduce chunks + transpose + split to MT bf16 pairs [g][hp][k]
__global__ void k_redT() {
    __shared__ float tile[32][33];
    int g = blockIdx.x, kt = blockIdx.y, ht = blockIdx.z;
    int tx = threadIdx.x, ty = threadIdx.y;
    int k = kt * 32 + ty, h = ht * 32 + tx;
    size_t base = ((size_t)k * G + g) * H + h;
    float s = 0.f;
#pragma unroll
    for (int c = 0; c < NCH4; c++) s += d_P[(size_t)c * H * G * H + base];
    tile[ty][tx] = s;
    __syncthreads();
    if (ty < 16) {
        float v0 = tile[tx][2 * ty];
        float v1 = tile[tx][2 * ty + 1];
        uint32_t b, sm;
        bsplit2(v0, v1, b, sm);
        int idx = (g * 64 + ht * 16 + ty) * H + kt * 32 + tx;
        d_MTBig[idx] = b;
        d_MTSml[idx] = sm;
    }
}

// ---------------- nodes init: tensor-core (ctx summed inline) ----------------
__global__ void __launch_bounds__(256) k_nodes0(const float* __restrict__ nemb,
                                                const float* __restrict__ bbil,
                                                const float* __restrict__ blm) {
    extern __shared__ uint32_t smem_u[];
    uint32_t* As_h = smem_u;
    uint32_t* As_l = smem_u + ASIZE;
    uint32_t* Bs_h = smem_u + 2 * ASIZE;
    uint32_t* Bs_l = smem_u + 2 * ASIZE + BSIZE;
    int gph = blockIdx.x, rb = blockIdx.y;
    int row0 = rb * 64;
    int tid = threadIdx.x;
    int lane = tid & 31, wid = tid >> 5;
    int g = lane >> 2, t = lane & 3, n0 = wid * 16;

#pragma unroll
    for (int it = 0; it < 16; it++) {
        int id = tid + 256 * it;
        int r = id >> 6, kp = id & 63;
        int lrow = row0 + r;
        float2 v;
        if (lrow >= NPG) v = make_float2(0.f, 0.f);
        else if (lrow == 0) {
            v = make_float2(blm[2 * kp], blm[2 * kp + 1]);
#pragma unroll
            for (int c = 0; c < NCH4; c++) {
                float2 p = *(const float2*)&d_Pc[((size_t)c * G + gph) * H + 2 * kp];
                v.x += p.x;
                v.y += p.y;
            }
        } else v = *(const float2*)&nemb[(size_t)(gph * NPG + lrow) * H + 2 * kp];
        uint32_t b, s;
        bsplit2(v.x, v.y, b, s);
        As_h[r * ASTR + kp] = b;
        As_l[r * ASTR + kp] = s;
    }
    const uint32_t* MB = d_MTBig + gph * 64 * H;
    const uint32_t* MS = d_MTSml + gph * 64 * H;
#pragma unroll
    for (int it = 0; it < 8; it++) {
        int id = tid + 256 * it;
        int hp = id >> 5, q = id & 31;
        *(uint4*)&Bs_h[hp * BSTR + q * 4] = *(const uint4*)&MB[hp * H + q * 4];
        *(uint4*)&Bs_l[hp * BSTR + q * 4] = *(const uint4*)&MS[hp * H + q * 4];
    }
    __syncthreads();

    float acc[4][2][4];
#pragma unroll
    for (int a = 0; a < 4; a++)
#pragma unroll
        for (int b = 0; b < 2; b++)
#pragma unroll
            for (int c = 0; c < 4; c++) acc[a][b][c] = 0.f;

#pragma unroll
    for (int s = 0; s < 8; s++)
        mma_step(As_h, As_l, Bs_h, Bs_l, acc, g, t, n0, s * 8);

#pragma unroll
    for (int mt = 0; mt < 4; mt++) {
#pragma unroll
        for (int nt = 0; nt < 2; nt++) {
            int col = n0 + nt * 8 + 2 * t;
            float b0 = bbil[col], b1 = bbil[col + 1];
            int lr0 = row0 + mt * 16 + g;
            if (lr0 < NPG)
                *(float2*)&d_nodes[(size_t)(gph * NPG + lr0) * H + col] =
                    make_float2(acc[mt][nt][0] + b0, acc[mt][nt][1] + b1);
            int lr1 = lr0 + 8;
            if (lr1 < NPG)
                *(float2*)&d_nodes[(size_t)(gph * NPG + lr1) * H + col] =
                    make_float2(acc[mt][nt][2] + b0, acc[mt][nt][3] + b1);
        }
    }
}

// ---------------- per-(hop, edge-type) attention scalar table --------------
__global__ void k_aet(const float* __restrict__ eemb, const float* __restrict__ linE,
                      const float* __restrict__ attE) {
    int i = blockIdx.x / NT, tt = blockIdx.x % NT;
    int c = threadIdx.x;
    const float* le = linE + (size_t)i * H * H;
    const float* em = eemb + (size_t)tt * H;
    float tmp = 0.f;
#pragma unroll 8
    for (int k = 0; k < H; k++) tmp += em[k] * le[(size_t)k * H + c];
    float v = tmp * attE[i * H + c];
    for (int o = 16; o > 0; o >>= 1) v += __shfl_xor_sync(0xffffffffu, v, o);
    __shared__ float ps[4];
    if ((threadIdx.x & 31) == 0) ps[threadIdx.x >> 5] = v;
    __syncthreads();
    if (threadIdx.x == 0) d_aet[i * NT + tt] = ps[0] + ps[1] + ps[2] + ps[3];
}

// ---------------- per-hop: h = nodes @ lin (tensor), fused a_src/a_dst -----
__global__ void __launch_bounds__(256) k_lin(int hop, const float* __restrict__ att_s,
                                             const float* __restrict__ att_d) {
    extern __shared__ uint32_t smem_u[];
    uint32_t* As_h = smem_u;
    uint32_t* As_l = smem_u + ASIZE;
    uint32_t* Bs_h = smem_u + 2 * ASIZE;
    uint32_t* Bs_l = smem_u + 2 * ASIZE + BSIZE;
    int row0 = blockIdx.x * 64;
    int tid = threadIdx.x;
    int lane = tid & 31, wid = tid >> 5;
    int g = lane >> 2, t = lane & 3, n0 = wid * 16;

#pragma unroll
    for (int it = 0; it < 16; it++) {
        int id = tid + 256 * it;
        int r = id >> 6, kp = id & 63;
        float2 v = *(const float2*)&d_nodes[(size_t)(row0 + r) * H + 2 * kp];
        uint32_t b, s;
        bsplit2(v.x, v.y, b, s);
        As_h[r * ASTR + kp] = b;
        As_l[r * ASTR + kp] = s;
    }
    const uint32_t* LB = d_linBig + hop * 64 * H;
    const uint32_t* LS = d_linSml + hop * 64 * H;
#pragma unroll
    for (int it = 0; it < 8; it++) {
        int id = tid + 256 * it;
        int kp = id >> 5, q = id & 31;
        *(uint4*)&Bs_h[kp * BSTR + q * 4] = *(const uint4*)&LB[kp * H + q * 4];
        *(uint4*)&Bs_l[kp * BSTR + q * 4] = *(const uint4*)&LS[kp * H + q * 4];
    }
    __syncthreads();

    float acc[4][2][4];
#pragma unroll
    for (int a = 0; a < 4; a++)
#pragma unroll
        for (int b = 0; b < 2; b++)
#pragma unroll
            for (int c = 0; c < 4; c++) acc[a][b][c] = 0.f;

#pragma unroll
    for (int s = 0; s < 8; s++)
        mma_step(As_h, As_l, Bs_h, Bs_l, acc, g, t, n0, s * 8);

#pragma unroll
    for (int mt = 0; mt < 4; mt++) {
        int row = row0 + mt * 16 + g;
#pragma unroll
        for (int nt = 0; nt < 2; nt++) {
            int col = n0 + nt * 8 + 2 * t;
            *(float2*)&d_hbuf[(size_t)row * H + col] = make_float2(acc[mt][nt][0], acc[mt][nt][1]);
            *(float2*)&d_hbuf[(size_t)(row + 8) * H + col] = make_float2(acc[mt][nt][2], acc[mt][nt][3]);
        }
    }

    float pS[4][2] = {{0.f, 0.f}, {0.f, 0.f}, {0.f, 0.f}, {0.f, 0.f}};
    float pD[4][2] = {{0.f, 0.f}, {0.f, 0.f}, {0.f, 0.f}, {0.f, 0.f}};
#pragma unroll
    for (int nt = 0; nt < 2; nt++) {
        int c0 = n0 + nt * 8 + 2 * t;
        float as0 = att_s[c0], as1 = att_s[c0 + 1];
        float ad0 = att_d[c0], ad1 = att_d[c0 + 1];
#pragma unroll
        for (int mt = 0; mt < 4; mt++) {
            pS[mt][0] += acc[mt][nt][0] * as0 + acc[mt][nt][1] * as1;
            pS[mt][1] += acc[mt][nt][2] * as0 + acc[mt][nt][3] * as1;
            pD[mt][0] += acc[mt][nt][0] * ad0 + acc[mt][nt][1] * ad1;
            pD[mt][1] += acc[mt][nt][2] * ad0 + acc[mt][nt][3] * ad1;
        }
    }
#pragma unroll
    for (int o = 1; o < 4; o <<= 1) {
#pragma unroll
        for (int mt = 0; mt < 4; mt++) {
#pragma unroll
            for (int hf = 0; hf < 2; hf++) {
                pS[mt][hf] += __shfl_xor_sync(0xffffffffu, pS[mt][hf], o);
                pD[mt][hf] += __shfl_xor_sync(0xffffffffu, pD[mt][hf], o);
            }
        }
    }
    __syncthreads();
    float* sS = (float*)smem_u;
    float* sD = (float*)smem_u + 512;
    if (t == 0) {
#pragma unroll
        for (int mt = 0; mt < 4; mt++) {
#pragma unroll
            for (int hf = 0; hf < 2; hf++) {
                int row = mt * 16 + hf * 8 + g;
                sS[wid * 64 + row] = pS[mt][hf];
                sD[wid * 64 + row] = pD[mt][hf];
            }
        }
    }
    __syncthreads();
    if (tid < 128) {
        int which = tid >> 6, row = tid & 63;
        const float* sp = which ? sD : sS;
        float s = 0.f;
#pragma unroll
        for (int w = 0; w < 8; w++) s += sp[w * 64 + row];
        if (which) d_adst[row0 + row] = s;
        else d_asrc[row0 + row] = s;
    }
}

// ---------------- per-hop: softmax attention + aggregate + gelu ------------
__global__ void k_gat(int hop, const float* __restrict__ bias) {
    int n = blockIdx.x * 8 + (threadIdx.x >> 5);
    int lane = threadIdx.x & 31;
    const float* aet = d_aet + hop * NT;
    int s0 = d_rowptr[n], s1 = d_rowptr[n + 1];
    int deg = s1 - s0;
    float adn = d_adst[n];
    float asn = d_asrc[n];

    int p_reg = 0;
    float lg_reg = 0.f;
    float m = -1e30f, s = 0.f, aes = 0.f;
    bool fast = (deg <= 32);

    if (fast) {
        if (lane < deg) {
            p_reg = d_csr[s0 + lane];
            float ae = aet[p_reg >> 20];
            lg_reg = lrelu(d_asrc[p_reg & 0xFFFFF] + adn + ae);
            aes = ae;
            m = lg_reg;
            s = 1.f;
        }
    } else {
        for (int e = s0 + lane; e < s1; e += 32) {
            int p = d_csr[e];
            float ae = aet[p >> 20];
            float lg = lrelu(d_asrc[p & 0xFFFFF] + adn + ae);
            d_lscr[e] = lg;
            aes += ae;
            float mn = fmaxf(m, lg);
            s = s * __expf(m - mn) + __expf(lg - mn);
            m = mn;
        }
        __syncwarp();
    }
#pragma unroll
    for (int o = 16; o > 0; o >>= 1) {
        float mo = __shfl_xor_sync(0xffffffffu, m, o);
        float so = __shfl_xor_sync(0xffffffffu, s, o);
        aes += __shfl_xor_sync(0xffffffffu, aes, o);
        float mn = fmaxf(m, mo);
        s = s * __expf(m - mn) + so * __expf(mo - mn);
        m = mn;
    }
    float aloop = aes / (float)(deg > 0 ? deg : 1);
    float slg = lrelu(asn + adn + aloop);
    float mf = fmaxf(m, slg);
    float sf = s * __expf(m - mf) + __expf(slg - mf);
    float inv = 1.f / sf;

    float4 a0 = make_float4(0.f, 0.f, 0.f, 0.f);
    float4 a1 = make_float4(0.f, 0.f, 0.f, 0.f);
    float4 a2 = make_float4(0.f, 0.f, 0.f, 0.f);
    float4 a3 = make_float4(0.f, 0.f, 0.f, 0.f);

    if (fast) {
        float w_reg = (lane < deg) ? __expf(lg_reg - mf) : 0.f;
        int j = 0;
        for (; j + 4 <= deg; j += 4) {
            int p0 = __shfl_sync(0xffffffffu, p_reg, j);
            int p1 = __shfl_sync(0xffffffffu, p_reg, j + 1);
            int p2 = __shfl_sync(0xffffffffu, p_reg, j + 2);
            int p3 = __shfl_sync(0xffffffffu, p_reg, j + 3);
            float w0 = __shfl_sync(0xffffffffu, w_reg, j);
            float w1 = __shfl_sync(0xffffffffu, w_reg, j + 1);
            float w2 = __shfl_sync(0xffffffffu, w_reg, j + 2);
            float w3 = __shfl_sync(0xffffffffu, w_reg, j + 3);
            float4 h0 = ((const float4*)(d_hbuf + (size_t)(p0 & 0xFFFFF) * H))[lane];
            float4 h1 = ((const float4*)(d_hbuf + (size_t)(p1 & 0xFFFFF) * H))[lane];
            float4 h2 = ((const float4*)(d_hbuf + (size_t)(p2 & 0xFFFFF) * H))[lane];
            float4 h3 = ((const float4*)(d_hbuf + (size_t)(p3 & 0xFFFFF) * H))[lane];
            a0.x += w0 * h0.x; a0.y += w0 * h0.y; a0.z += w0 * h0.z; a0.w += w0 * h0.w;
            a1.x += w1 * h1.x; a1.y += w1 * h1.y; a1.z += w1 * h1.z; a1.w += w1 * h1.w;
            a2.x += w2 * h2.x; a2.y += w2 * h2.y; a2.z += w2 * h2.z; a2.w += w2 * h2.w;
            a3.x += w3 * h3.x; a3.y += w3 * h3.y; a3.z += w3 * h3.z; a3.w += w3 * h3.w;
        }
        for (; j < deg; j++) {
            int p0 = __shfl_sync(0xffffffffu, p_reg, j);
            float w0 = __shfl_sync(0xffffffffu, w_reg, j);
            float4 h0 = ((const float4*)(d_hbuf + (size_t)(p0 & 0xFFFFF) * H))[lane];
            a0.x += w0 * h0.x; a0.y += w0 * h0.y; a0.z += w0 * h0.z; a0.w += w0 * h0.w;
        }
    } else {
        for (int e = s0; e < s1; ++e) {
            int p = d_csr[e];
            float w = __expf(d_lscr[e] - mf);
            float4 hv = ((const float4*)(d_hbuf + (size_t)(p & 0xFFFFF) * H))[lane];
            a0.x += w * hv.x; a0.y += w * hv.y;
            a0.z += w * hv.z; a0.w += w * hv.w;
        }
    }

    float ws = __expf(slg - mf);
    float4 hn = ((const float4*)(d_hbuf + (size_t)n * H))[lane];
    a0.x += a1.x + a2.x + a3.x + ws * hn.x;
    a0.y += a1.y + a2.y + a3.y + ws * hn.y;
    a0.z += a1.z + a2.z + a3.z + ws * hn.z;
    a0.w += a1.w + a2.w + a3.w + ws * hn.w;

    float4 b = ((const float4*)bias)[lane];
    float4 o;
    o.x = gelu_exact(a0.x * inv + b.x);
    o.y = gelu_exact(a0.y * inv + b.y);
    o.z = gelu_exact(a0.z * inv + b.z);
    o.w = gelu_exact(a0.w * inv + b.w);
    ((float4*)(d_nodes + (size_t)n * H))[lane] = o;
}

// ---------------- output gather ----------------
__global__ void k_out(const int* __restrict__ ctxn, float* __restrict__ out) {
    int g = blockIdx.x, k = threadIdx.x;
    out[g * H + k] = d_nodes[(size_t)ctxn[g] * H + k];
}

// ---------------- launch ----------------
extern "C" void kernel_launch(void* const* d_in, const int* in_sizes, int n_in,
                              void* d_out, int out_size) {
    (void)in_sizes; (void)n_in; (void)out_size;
    const float* lm   = (const float*)d_in[0];
    const float* nemb = (const float*)d_in[1];
    const float* Wlm  = (const float*)d_in[2];
    const float* blm  = (const float*)d_in[3];
    const float* Wbil = (const float*)d_in[4];
    const float* bbil = (const float*)d_in[5];
    const float* eemb = (const float*)d_in[6];
    const float* glin = (const float*)d_in[7];
    const float* gas  = (const float*)d_in[8];
    const float* gad  = (const float*)d_in[9];
    const float* gle  = (const float*)d_in[10];
    const float* gae  = (const float*)d_in[11];
    const float* gb   = (const float*)d_in[12];
    const int* ei     = (const int*)d_in[13];
    const int* et     = (const int*)d_in[14];
    const int* ctxn   = (const int*)d_in[16];
    float* out = (float*)d_out;

    cudaFuncSetAttribute(k_bil, cudaFuncAttributeMaxDynamicSharedMemorySize, BIL_SMEM);
    cudaFuncSetAttribute(k_nodes0, cudaFuncAttributeMaxDynamicSharedMemorySize, SMEM_BYTES);
    cudaFuncSetAttribute(k_lin, cudaFuncAttributeMaxDynamicSharedMemorySize, SMEM_BYTES);

    // k_bil kept as 4th launch for the ncu capture window
    k_prep_lm<<<128, 256>>>(lm);
    k_init<<<(N_NODES + 255) / 256, 256>>>();
    k_count<<<(N_EDGES + 255) / 256, 256>>>(ei);
    k_bil<<<dim3(H + 1, NCH4), 256, BIL_SMEM>>>(Wbil, Wlm);
    k_scan<<<1, 1024>>>();
    k_scatter<<<(N_EDGES + 255) / 256, 256>>>(ei, et);
    k_prep_lin<<<160, 256>>>(glin);
    k_redT<<<dim3(G, 4, 4), dim3(32, 32)>>>();
    k_nodes0<<<dim3(G, 4), 256, SMEM_BYTES>>>(nemb, bbil, blm);
    k_aet<<<HOPS * NT, 128>>>(eemb, gle, gae);

    for (int hop = 0; hop < HOPS; hop++) {
        k_lin<<<N_NODES / 64, 256, SMEM_BYTES>>>(hop, gas + (size_t)hop * H,
                                                 gad + (size_t)hop * H);
        k_gat<<<N_NODES / 8, 256>>>(hop, gb + (size_t)hop * H);
    }

    k_out<<<G, 128>>>(ctxn, out);
}